// round 1
// baseline (speedup 1.0000x reference)
#include <cuda_runtime.h>

// Fixed problem shape (from reference setup_inputs)
constexpr int Bb = 4;
constexpr int Ts = 2048;
constexpr int Dd = 1024;
constexpr int Hh = 16;
constexpr int HD = 64;
constexpr int Mrows = Bb * Ts;  // 8192

// Scratch (device globals: allocation-free per harness rules)
__device__ float g_Q[(size_t)Bb * Hh * Ts * HD];
__device__ float g_K[(size_t)Bb * Hh * Ts * HD];
__device__ float g_V[(size_t)Bb * Hh * Ts * HD];
__device__ float g_attn[(size_t)Bb * Ts * Dd];

// ---------------------------------------------------------------------------
// SGEMM: C[m,n] = sum_k A[m,k] * W[n,k]  (i.e. A @ W^T), M=8192, N=K=1024.
// 128x128 tile, BK=8, 256 threads, 8x8 per-thread microtile.
// HEAD_LAYOUT: scatter output into [B, H, T, Hd] (for Q/K/V projections).
// ---------------------------------------------------------------------------
template <bool HEAD_LAYOUT>
__global__ void __launch_bounds__(256, 2)
sgemm_nt(const float* __restrict__ A, const float* __restrict__ Wt,
         float* __restrict__ C, const float* __restrict__ bias) {
    constexpr int K = Dd;
    __shared__ float As[8][128];
    __shared__ float Bs[8][128];

    const int tid = threadIdx.x;
    const int tx = tid & 15;        // 0..15  -> n
    const int ty = tid >> 4;        // 0..15  -> m
    const int bm = blockIdx.y * 128;
    const int bn = blockIdx.x * 128;

    // loader mapping: one float4 of A and one of W per thread per k-tile
    const int lrow = tid >> 1;           // 0..127
    const int lq = (tid & 1) * 4;        // 0 or 4

    const float* Aptr = A + (size_t)(bm + lrow) * K + lq;
    const float* Bptr = Wt + (size_t)(bn + lrow) * K + lq;

    float acc[8][8];
#pragma unroll
    for (int i = 0; i < 8; i++)
#pragma unroll
        for (int j = 0; j < 8; j++) acc[i][j] = 0.f;

    for (int k0 = 0; k0 < K; k0 += 8) {
        float4 av = *(const float4*)(Aptr + k0);
        float4 bv = *(const float4*)(Bptr + k0);
        As[lq + 0][lrow] = av.x;
        As[lq + 1][lrow] = av.y;
        As[lq + 2][lrow] = av.z;
        As[lq + 3][lrow] = av.w;
        Bs[lq + 0][lrow] = bv.x;
        Bs[lq + 1][lrow] = bv.y;
        Bs[lq + 2][lrow] = bv.z;
        Bs[lq + 3][lrow] = bv.w;
        __syncthreads();
#pragma unroll
        for (int k = 0; k < 8; k++) {
            float a[8], b[8];
#pragma unroll
            for (int i = 0; i < 8; i++) a[i] = As[k][ty * 8 + i];
#pragma unroll
            for (int j = 0; j < 8; j++) b[j] = Bs[k][tx * 8 + j];
#pragma unroll
            for (int i = 0; i < 8; i++)
#pragma unroll
                for (int j = 0; j < 8; j++)
                    acc[i][j] = fmaf(a[i], b[j], acc[i][j]);
        }
        __syncthreads();
    }

#pragma unroll
    for (int i = 0; i < 8; i++) {
        const int m = bm + ty * 8 + i;
#pragma unroll
        for (int j = 0; j < 8; j++) {
            const int n = bn + tx * 8 + j;
            float v = acc[i][j];
            if (bias != nullptr) v += bias[n];
            if (HEAD_LAYOUT) {
                const int b_ = m >> 11;         // m / T  (T=2048)
                const int t_ = m & (Ts - 1);
                const int h_ = n >> 6;          // n / 64
                const int d_ = n & 63;
                C[(((size_t)(b_ * Hh + h_) * Ts + t_) << 6) + d_] = v;
            } else {
                C[(size_t)m * Dd + n] = v;
            }
        }
    }
}

// ---------------------------------------------------------------------------
// Flash attention, fp32, causal. One CTA per (64-query block, head).
// 256 threads as 16x16: thread (tr,tc) owns a 4x4 score/output microtile.
// SMEM: Qs[64x64], KPs[64x64] (K^T tile, then reused for P), Vs[64x64] = 48KB.
// ---------------------------------------------------------------------------
__global__ void __launch_bounds__(256, 2) flash_attn() {
    __shared__ float Qs[64 * 64];
    __shared__ float KPs[64 * 64];
    __shared__ float Vs[64 * 64];

    const int tid = threadIdx.x;
    const int tc = tid & 15;
    const int tr = tid >> 4;
    const int qb = blockIdx.x;    // 0..31
    const int bh = blockIdx.y;    // 0..63 = b*H + h
    const int q0 = qb * 64;

    const float* Qg = g_Q + (size_t)bh * Ts * HD;
    const float* Kg = g_K + (size_t)bh * Ts * HD;
    const float* Vg = g_V + (size_t)bh * Ts * HD;

    const int lrow = tid >> 2;          // 0..63 (token row)
    const int lcol = (tid & 3) * 16;    // 0,16,32,48 (dim chunk)

    // Load Q block, fold in softmax scale 1/sqrt(64) = 0.125
#pragma unroll
    for (int x = 0; x < 16; x += 4) {
        float4 v = *(const float4*)(Qg + (size_t)(q0 + lrow) * HD + lcol + x);
        Qs[lrow * 64 + lcol + x + 0] = v.x * 0.125f;
        Qs[lrow * 64 + lcol + x + 1] = v.y * 0.125f;
        Qs[lrow * 64 + lcol + x + 2] = v.z * 0.125f;
        Qs[lrow * 64 + lcol + x + 3] = v.w * 0.125f;
    }

    float m_i[4], l_i[4], o[4][4];
#pragma unroll
    for (int i = 0; i < 4; i++) {
        m_i[i] = -1e30f;
        l_i[i] = 0.f;
#pragma unroll
        for (int j = 0; j < 4; j++) o[i][j] = 0.f;
    }
    const int rbase = tr * 4;
    const int cbase = tc * 4;

    for (int kb = 0; kb <= qb; kb++) {
        const int k0 = kb * 64;
        __syncthreads();  // protect KPs/Vs from previous iteration's readers
        // Load K (transposed: KPs[dim*64 + token]) and V (row-major)
#pragma unroll
        for (int x = 0; x < 16; x += 4) {
            float4 kv = *(const float4*)(Kg + (size_t)(k0 + lrow) * HD + lcol + x);
            KPs[(lcol + x + 0) * 64 + lrow] = kv.x;
            KPs[(lcol + x + 1) * 64 + lrow] = kv.y;
            KPs[(lcol + x + 2) * 64 + lrow] = kv.z;
            KPs[(lcol + x + 3) * 64 + lrow] = kv.w;
            float4 vv = *(const float4*)(Vg + (size_t)(k0 + lrow) * HD + lcol + x);
            *(float4*)&Vs[lrow * 64 + lcol + x] = vv;
        }
        __syncthreads();

        // S = Q . K^T (scale pre-folded)
        float s[4][4];
#pragma unroll
        for (int i = 0; i < 4; i++)
#pragma unroll
            for (int j = 0; j < 4; j++) s[i][j] = 0.f;
#pragma unroll
        for (int k = 0; k < 64; k++) {
            float4 kv = *(const float4*)&KPs[k * 64 + cbase];
#pragma unroll
            for (int i = 0; i < 4; i++) {
                const float qv = Qs[(rbase + i) * 64 + k];
                s[i][0] = fmaf(qv, kv.x, s[i][0]);
                s[i][1] = fmaf(qv, kv.y, s[i][1]);
                s[i][2] = fmaf(qv, kv.z, s[i][2]);
                s[i][3] = fmaf(qv, kv.w, s[i][3]);
            }
        }

        // Causal mask only on the diagonal block (k0 == q0)
        if (kb == qb) {
#pragma unroll
            for (int i = 0; i < 4; i++)
#pragma unroll
                for (int j = 0; j < 4; j++)
                    if (cbase + j > rbase + i) s[i][j] = -1e30f;
        }

        // Online softmax (rows live on 16 contiguous lanes of a warp half)
#pragma unroll
        for (int i = 0; i < 4; i++) {
            float rm = fmaxf(fmaxf(s[i][0], s[i][1]), fmaxf(s[i][2], s[i][3]));
#pragma unroll
            for (int off = 1; off < 16; off <<= 1)
                rm = fmaxf(rm, __shfl_xor_sync(0xffffffffu, rm, off));
            const float mn = fmaxf(m_i[i], rm);
            const float corr = __expf(m_i[i] - mn);
            m_i[i] = mn;
            l_i[i] *= corr;
#pragma unroll
            for (int j = 0; j < 4; j++) o[i][j] *= corr;
            float rs = 0.f;
#pragma unroll
            for (int j = 0; j < 4; j++) {
                s[i][j] = __expf(s[i][j] - mn);
                rs += s[i][j];
            }
#pragma unroll
            for (int off = 1; off < 16; off <<= 1)
                rs += __shfl_xor_sync(0xffffffffu, rs, off);
            l_i[i] += rs;
        }

        // Publish P into the K buffer (all reads of K are done)
        __syncthreads();
#pragma unroll
        for (int i = 0; i < 4; i++)
            *(float4*)&KPs[(rbase + i) * 64 + cbase] =
                make_float4(s[i][0], s[i][1], s[i][2], s[i][3]);
        __syncthreads();

        // O += P . V
#pragma unroll
        for (int k = 0; k < 64; k++) {
            float4 vv = *(const float4*)&Vs[k * 64 + cbase];
#pragma unroll
            for (int i = 0; i < 4; i++) {
                const float pv = KPs[(rbase + i) * 64 + k];
                o[i][0] = fmaf(pv, vv.x, o[i][0]);
                o[i][1] = fmaf(pv, vv.y, o[i][1]);
                o[i][2] = fmaf(pv, vv.z, o[i][2]);
                o[i][3] = fmaf(pv, vv.w, o[i][3]);
            }
        }
    }

    // Epilogue: normalize and scatter to [B, T, D] (D index = h*64 + d)
    const int b_ = bh >> 4;   // / H
    const int h_ = bh & 15;   // % H
    float* outp = g_attn + (size_t)(b_ * Ts + q0 + rbase) * Dd + h_ * HD + cbase;
#pragma unroll
    for (int i = 0; i < 4; i++) {
        const float inv = 1.f / l_i[i];
        *(float4*)(outp + (size_t)i * Dd) =
            make_float4(o[i][0] * inv, o[i][1] * inv, o[i][2] * inv, o[i][3] * inv);
    }
}

// ---------------------------------------------------------------------------
extern "C" void kernel_launch(void* const* d_in, const int* in_sizes, int n_in,
                              void* d_out, int out_size) {
    const float* xq = (const float*)d_in[0];
    const float* xk = (const float*)d_in[1];
    const float* xv = (const float*)d_in[2];
    const float* Wq = (const float*)d_in[3];
    const float* Wk = (const float*)d_in[4];
    const float* Wv = (const float*)d_in[5];
    const float* Wo = (const float*)d_in[6];
    const float* bo = (const float*)d_in[7];
    float* out = (float*)d_out;

    float *gq, *gk, *gv, *ga;
    cudaGetSymbolAddress((void**)&gq, g_Q);
    cudaGetSymbolAddress((void**)&gk, g_K);
    cudaGetSymbolAddress((void**)&gv, g_V);
    cudaGetSymbolAddress((void**)&ga, g_attn);

    dim3 gemm_grid(Dd / 128, Mrows / 128);  // (8, 64)
    sgemm_nt<true><<<gemm_grid, 256>>>(xq, Wq, gq, nullptr);
    sgemm_nt<true><<<gemm_grid, 256>>>(xk, Wk, gk, nullptr);
    sgemm_nt<true><<<gemm_grid, 256>>>(xv, Wv, gv, nullptr);
    flash_attn<<<dim3(Ts / 64, Bb * Hh), 256>>>();
    sgemm_nt<false><<<gemm_grid, 256>>>(ga, Wo, out, bo);
}

// round 3
// speedup vs baseline: 1.6621x; 1.6621x over previous
#include <cuda_runtime.h>
#include <cuda_bf16.h>
#include <cstdint>

// Fixed problem shape
constexpr int Bb = 4;
constexpr int Ts = 2048;
constexpr int Dd = 1024;
constexpr int Hh = 16;
constexpr int HD = 64;
constexpr int Mrows = Bb * Ts;  // 8192

// Scratch
__device__ float g_Q[(size_t)Bb * Hh * Ts * HD];
__device__ float g_K[(size_t)Bb * Hh * Ts * HD];
__device__ float g_V[(size_t)Bb * Hh * Ts * HD];
__device__ float g_attn[(size_t)Bb * Ts * Dd];

// ---------------------------------------------------------------------------
// Warp-level bf16 MMA (sm_80+ path; works on plain sm_103 target)
// ---------------------------------------------------------------------------
__device__ __forceinline__ void mma_bf16(float* d, const uint32_t* a, const uint32_t* b) {
    asm volatile(
        "mma.sync.aligned.m16n8k16.row.col.f32.bf16.bf16.f32 "
        "{%0,%1,%2,%3}, {%4,%5,%6,%7}, {%8,%9}, {%0,%1,%2,%3};"
        : "+f"(d[0]), "+f"(d[1]), "+f"(d[2]), "+f"(d[3])
        : "r"(a[0]), "r"(a[1]), "r"(a[2]), "r"(a[3]), "r"(b[0]), "r"(b[1]));
}

// ---------------------------------------------------------------------------
// bf16x3 GEMM: C[m,n] = sum_k A[m,k] * W[n,k]  (A @ W^T)
// M=8192, N=K=1024. 128x128 tile, BK=32, 256 threads, 8 warps as 2(m)x4(n).
// fp32 split into bf16 hi+lo; 3 MMA terms (hi*hi + hi*lo + lo*hi).
// SMEM rows padded: stride 20 u32 (16 data + 4 pad) -> conflict-free frags.
// ---------------------------------------------------------------------------
constexpr int RS = 20;                 // row stride in u32 (32 bf16 + 8 pad)
constexpr int TILE_U32 = 128 * RS;     // 2560 u32 per (matrix, term)
constexpr int SM_U32_TOTAL = 8 * TILE_U32;  // 2 stages * 4 tiles = 81920 B

template <bool HEAD_LAYOUT>
__global__ void __launch_bounds__(256)
bf16x3_gemm(const float* __restrict__ A, const float* __restrict__ W,
            float* __restrict__ C, const float* __restrict__ bias) {
    extern __shared__ uint32_t sm[];
    const int tid = threadIdx.x;
    const int lane = tid & 31;
    const int warp = tid >> 5;
    const int g = lane >> 2;   // fragment group row
    const int t = lane & 3;    // fragment group col
    const int bm = blockIdx.y * 128;
    const int bn = blockIdx.x * 128;
    const int wm = (warp >> 2) * 64;  // warp m offset (0 or 64)
    const int wn = (warp & 3) * 32;   // warp n offset

    // loader mapping: c in [0,1024): row = c>>3 (0..127), q = c&7 (float4 idx)
    const int lrow = tid >> 3;               // rows 0..31 handled per iter step
    // Actually: c = tid + i*256 -> row = c>>3, q = c&7

    float acc[4][4][4];
#pragma unroll
    for (int mi = 0; mi < 4; mi++)
#pragma unroll
        for (int ni = 0; ni < 4; ni++)
#pragma unroll
            for (int r = 0; r < 4; r++) acc[mi][ni][r] = 0.f;

    float4 ra[4], rb[4];
    const float* Ag = A + (size_t)bm * Dd;
    const float* Wg = W + (size_t)bn * Dd;

    // prologue loads (kc = 0)
#pragma unroll
    for (int i = 0; i < 4; i++) {
        const int c = tid + i * 256;
        const int row = c >> 3, q = c & 7;
        ra[i] = *(const float4*)(Ag + (size_t)row * Dd + q * 4);
        rb[i] = *(const float4*)(Wg + (size_t)row * Dd + q * 4);
    }

    for (int kc = 0; kc < Dd / 32; kc++) {
        const int st = kc & 1;
        uint32_t* sAh = sm + (st * 4 + 0) * TILE_U32;
        uint32_t* sAl = sm + (st * 4 + 1) * TILE_U32;
        uint32_t* sBh = sm + (st * 4 + 2) * TILE_U32;
        uint32_t* sBl = sm + (st * 4 + 3) * TILE_U32;

        // convert + store current tile
#pragma unroll
        for (int i = 0; i < 4; i++) {
            const int c = tid + i * 256;
            const int row = c >> 3, q = c & 7;
            const int so = row * RS + q * 2;
            {
                float4 v = ra[i];
                __nv_bfloat162 h01 = __floats2bfloat162_rn(v.x, v.y);
                __nv_bfloat162 h23 = __floats2bfloat162_rn(v.z, v.w);
                float2 f01 = __bfloat1622float2(h01);
                float2 f23 = __bfloat1622float2(h23);
                __nv_bfloat162 l01 = __floats2bfloat162_rn(v.x - f01.x, v.y - f01.y);
                __nv_bfloat162 l23 = __floats2bfloat162_rn(v.z - f23.x, v.w - f23.y);
                sAh[so] = *(uint32_t*)&h01;
                sAh[so + 1] = *(uint32_t*)&h23;
                sAl[so] = *(uint32_t*)&l01;
                sAl[so + 1] = *(uint32_t*)&l23;
            }
            {
                float4 v = rb[i];
                __nv_bfloat162 h01 = __floats2bfloat162_rn(v.x, v.y);
                __nv_bfloat162 h23 = __floats2bfloat162_rn(v.z, v.w);
                float2 f01 = __bfloat1622float2(h01);
                float2 f23 = __bfloat1622float2(h23);
                __nv_bfloat162 l01 = __floats2bfloat162_rn(v.x - f01.x, v.y - f01.y);
                __nv_bfloat162 l23 = __floats2bfloat162_rn(v.z - f23.x, v.w - f23.y);
                sBh[so] = *(uint32_t*)&h01;
                sBh[so + 1] = *(uint32_t*)&h23;
                sBl[so] = *(uint32_t*)&l01;
                sBl[so + 1] = *(uint32_t*)&l23;
            }
        }
        __syncthreads();

        // prefetch next k-chunk
        if (kc + 1 < Dd / 32) {
            const float* An = Ag + (kc + 1) * 32;
            const float* Wn = Wg + (kc + 1) * 32;
#pragma unroll
            for (int i = 0; i < 4; i++) {
                const int c = tid + i * 256;
                const int row = c >> 3, q = c & 7;
                ra[i] = *(const float4*)(An + (size_t)row * Dd + q * 4);
                rb[i] = *(const float4*)(Wn + (size_t)row * Dd + q * 4);
            }
        }

        // compute: 2 k16 steps
#pragma unroll
        for (int s = 0; s < 2; s++) {
            const int ko = s * 8;
            uint32_t ah[4][4], al[4][4];
#pragma unroll
            for (int mi = 0; mi < 4; mi++) {
                const int base = (wm + mi * 16 + g) * RS + ko + t;
                ah[mi][0] = sAh[base];
                ah[mi][1] = sAh[base + 8 * RS];
                ah[mi][2] = sAh[base + 4];
                ah[mi][3] = sAh[base + 8 * RS + 4];
                al[mi][0] = sAl[base];
                al[mi][1] = sAl[base + 8 * RS];
                al[mi][2] = sAl[base + 4];
                al[mi][3] = sAl[base + 8 * RS + 4];
            }
            uint32_t bh[4][2], bl[4][2];
#pragma unroll
            for (int ni = 0; ni < 4; ni++) {
                const int base = (wn + ni * 8 + g) * RS + ko + t;
                bh[ni][0] = sBh[base];
                bh[ni][1] = sBh[base + 4];
                bl[ni][0] = sBl[base];
                bl[ni][1] = sBl[base + 4];
            }
#pragma unroll
            for (int mi = 0; mi < 4; mi++)
#pragma unroll
                for (int ni = 0; ni < 4; ni++) {
                    mma_bf16(acc[mi][ni], ah[mi], bh[ni]);
                    mma_bf16(acc[mi][ni], ah[mi], bl[ni]);
                    mma_bf16(acc[mi][ni], al[mi], bh[ni]);
                }
        }
        __syncthreads();
    }

    // epilogue
#pragma unroll
    for (int mi = 0; mi < 4; mi++) {
        const int m0 = bm + wm + mi * 16 + g;
#pragma unroll
        for (int ni = 0; ni < 4; ni++) {
            const int n = bn + wn + ni * 8 + 2 * t;
            float c0 = acc[mi][ni][0], c1 = acc[mi][ni][1];
            float c2 = acc[mi][ni][2], c3 = acc[mi][ni][3];
            if (!HEAD_LAYOUT) {
                const float bx = bias[n], by = bias[n + 1];
                *(float2*)(C + (size_t)m0 * Dd + n) = make_float2(c0 + bx, c1 + by);
                *(float2*)(C + (size_t)(m0 + 8) * Dd + n) = make_float2(c2 + bx, c3 + by);
            } else {
                const int h_ = n >> 6, d_ = n & 63;
                {
                    const int b_ = m0 >> 11, t_ = m0 & (Ts - 1);
                    float* p = C + (((size_t)(b_ * Hh + h_) * Ts + t_) << 6) + d_;
                    *(float2*)p = make_float2(c0, c1);
                }
                {
                    const int m1 = m0 + 8;
                    const int b_ = m1 >> 11, t_ = m1 & (Ts - 1);
                    float* p = C + (((size_t)(b_ * Hh + h_) * Ts + t_) << 6) + d_;
                    *(float2*)p = make_float2(c2, c3);
                }
            }
        }
    }
}

// ---------------------------------------------------------------------------
// Flash attention, fp32, causal (unchanged — known correct).
// ---------------------------------------------------------------------------
__global__ void __launch_bounds__(256, 2) flash_attn() {
    __shared__ float Qs[64 * 64];
    __shared__ float KPs[64 * 64];
    __shared__ float Vs[64 * 64];

    const int tid = threadIdx.x;
    const int tc = tid & 15;
    const int tr = tid >> 4;
    const int qb = blockIdx.x;
    const int bh = blockIdx.y;
    const int q0 = qb * 64;

    const float* Qg = g_Q + (size_t)bh * Ts * HD;
    const float* Kg = g_K + (size_t)bh * Ts * HD;
    const float* Vg = g_V + (size_t)bh * Ts * HD;

    const int lrow = tid >> 2;
    const int lcol = (tid & 3) * 16;

#pragma unroll
    for (int x = 0; x < 16; x += 4) {
        float4 v = *(const float4*)(Qg + (size_t)(q0 + lrow) * HD + lcol + x);
        Qs[lrow * 64 + lcol + x + 0] = v.x * 0.125f;
        Qs[lrow * 64 + lcol + x + 1] = v.y * 0.125f;
        Qs[lrow * 64 + lcol + x + 2] = v.z * 0.125f;
        Qs[lrow * 64 + lcol + x + 3] = v.w * 0.125f;
    }

    float m_i[4], l_i[4], o[4][4];
#pragma unroll
    for (int i = 0; i < 4; i++) {
        m_i[i] = -1e30f;
        l_i[i] = 0.f;
#pragma unroll
        for (int j = 0; j < 4; j++) o[i][j] = 0.f;
    }
    const int rbase = tr * 4;
    const int cbase = tc * 4;

    for (int kb = 0; kb <= qb; kb++) {
        const int k0 = kb * 64;
        __syncthreads();
#pragma unroll
        for (int x = 0; x < 16; x += 4) {
            float4 kv = *(const float4*)(Kg + (size_t)(k0 + lrow) * HD + lcol + x);
            KPs[(lcol + x + 0) * 64 + lrow] = kv.x;
            KPs[(lcol + x + 1) * 64 + lrow] = kv.y;
            KPs[(lcol + x + 2) * 64 + lrow] = kv.z;
            KPs[(lcol + x + 3) * 64 + lrow] = kv.w;
            float4 vv = *(const float4*)(Vg + (size_t)(k0 + lrow) * HD + lcol + x);
            *(float4*)&Vs[lrow * 64 + lcol + x] = vv;
        }
        __syncthreads();

        float s[4][4];
#pragma unroll
        for (int i = 0; i < 4; i++)
#pragma unroll
            for (int j = 0; j < 4; j++) s[i][j] = 0.f;
#pragma unroll
        for (int k = 0; k < 64; k++) {
            float4 kv = *(const float4*)&KPs[k * 64 + cbase];
#pragma unroll
            for (int i = 0; i < 4; i++) {
                const float qv = Qs[(rbase + i) * 64 + k];
                s[i][0] = fmaf(qv, kv.x, s[i][0]);
                s[i][1] = fmaf(qv, kv.y, s[i][1]);
                s[i][2] = fmaf(qv, kv.z, s[i][2]);
                s[i][3] = fmaf(qv, kv.w, s[i][3]);
            }
        }

        if (kb == qb) {
#pragma unroll
            for (int i = 0; i < 4; i++)
#pragma unroll
                for (int j = 0; j < 4; j++)
                    if (cbase + j > rbase + i) s[i][j] = -1e30f;
        }

#pragma unroll
        for (int i = 0; i < 4; i++) {
            float rm = fmaxf(fmaxf(s[i][0], s[i][1]), fmaxf(s[i][2], s[i][3]));
#pragma unroll
            for (int off = 1; off < 16; off <<= 1)
                rm = fmaxf(rm, __shfl_xor_sync(0xffffffffu, rm, off));
            const float mn = fmaxf(m_i[i], rm);
            const float corr = __expf(m_i[i] - mn);
            m_i[i] = mn;
            l_i[i] *= corr;
#pragma unroll
            for (int j = 0; j < 4; j++) o[i][j] *= corr;
            float rs = 0.f;
#pragma unroll
            for (int j = 0; j < 4; j++) {
                s[i][j] = __expf(s[i][j] - mn);
                rs += s[i][j];
            }
#pragma unroll
            for (int off = 1; off < 16; off <<= 1)
                rs += __shfl_xor_sync(0xffffffffu, rs, off);
            l_i[i] += rs;
        }

        __syncthreads();
#pragma unroll
        for (int i = 0; i < 4; i++)
            *(float4*)&KPs[(rbase + i) * 64 + cbase] =
                make_float4(s[i][0], s[i][1], s[i][2], s[i][3]);
        __syncthreads();

#pragma unroll
        for (int k = 0; k < 64; k++) {
            float4 vv = *(const float4*)&Vs[k * 64 + cbase];
#pragma unroll
            for (int i = 0; i < 4; i++) {
                const float pv = KPs[(rbase + i) * 64 + k];
                o[i][0] = fmaf(pv, vv.x, o[i][0]);
                o[i][1] = fmaf(pv, vv.y, o[i][1]);
                o[i][2] = fmaf(pv, vv.z, o[i][2]);
                o[i][3] = fmaf(pv, vv.w, o[i][3]);
            }
        }
    }

    const int b_ = bh >> 4;
    const int h_ = bh & 15;
    float* outp = g_attn + (size_t)(b_ * Ts + q0 + rbase) * Dd + h_ * HD + cbase;
#pragma unroll
    for (int i = 0; i < 4; i++) {
        const float inv = 1.f / l_i[i];
        *(float4*)(outp + (size_t)i * Dd) =
            make_float4(o[i][0] * inv, o[i][1] * inv, o[i][2] * inv, o[i][3] * inv);
    }
}

// ---------------------------------------------------------------------------
extern "C" void kernel_launch(void* const* d_in, const int* in_sizes, int n_in,
                              void* d_out, int out_size) {
    const float* xq = (const float*)d_in[0];
    const float* xk = (const float*)d_in[1];
    const float* xv = (const float*)d_in[2];
    const float* Wq = (const float*)d_in[3];
    const float* Wk = (const float*)d_in[4];
    const float* Wv = (const float*)d_in[5];
    const float* Wo = (const float*)d_in[6];
    const float* bo = (const float*)d_in[7];
    float* out = (float*)d_out;

    float *gq, *gk, *gv, *ga;
    cudaGetSymbolAddress((void**)&gq, g_Q);
    cudaGetSymbolAddress((void**)&gk, g_K);
    cudaGetSymbolAddress((void**)&gv, g_V);
    cudaGetSymbolAddress((void**)&ga, g_attn);

    const int smem_bytes = SM_U32_TOTAL * 4;  // 81920
    cudaFuncSetAttribute(bf16x3_gemm<true>,
                         cudaFuncAttributeMaxDynamicSharedMemorySize, smem_bytes);
    cudaFuncSetAttribute(bf16x3_gemm<false>,
                         cudaFuncAttributeMaxDynamicSharedMemorySize, smem_bytes);

    dim3 grid(Dd / 128, Mrows / 128);  // (8, 64)
    bf16x3_gemm<true><<<grid, 256, smem_bytes>>>(xq, Wq, gq, nullptr);
    bf16x3_gemm<true><<<grid, 256, smem_bytes>>>(xk, Wk, gk, nullptr);
    bf16x3_gemm<true><<<grid, 256, smem_bytes>>>(xv, Wv, gv, nullptr);
    flash_attn<<<dim3(Ts / 64, Bb * Hh), 256>>>();
    bf16x3_gemm<false><<<grid, 256, smem_bytes>>>(ga, Wo, out, bo);
}

// round 4
// speedup vs baseline: 2.4967x; 1.5021x over previous
#include <cuda_runtime.h>
#include <cuda_bf16.h>
#include <cstdint>

// Fixed problem shape
constexpr int Bb = 4;
constexpr int Ts = 2048;
constexpr int Dd = 1024;
constexpr int Hh = 16;
constexpr int HD = 64;
constexpr int Mrows = Bb * Ts;  // 8192

// Scratch
__device__ float g_Q[(size_t)Bb * Hh * Ts * HD];
__device__ float g_K[(size_t)Bb * Hh * Ts * HD];
__device__ float g_V[(size_t)Bb * Hh * Ts * HD];
__device__ float g_attn[(size_t)Bb * Ts * Dd];

// ---------------------------------------------------------------------------
// Warp-level bf16 MMA (sm_80+ path)
// ---------------------------------------------------------------------------
__device__ __forceinline__ void mma_bf16(float* d, const uint32_t* a, const uint32_t* b) {
    asm volatile(
        "mma.sync.aligned.m16n8k16.row.col.f32.bf16.bf16.f32 "
        "{%0,%1,%2,%3}, {%4,%5,%6,%7}, {%8,%9}, {%0,%1,%2,%3};"
        : "+f"(d[0]), "+f"(d[1]), "+f"(d[2]), "+f"(d[3])
        : "r"(a[0]), "r"(a[1]), "r"(a[2]), "r"(a[3]), "r"(b[0]), "r"(b[1]));
}

// split two floats into bf16 hi pair + lo (residual) pair, packed u32
__device__ __forceinline__ void split2(float a, float b, uint32_t& h, uint32_t& l) {
    __nv_bfloat162 hb = __floats2bfloat162_rn(a, b);
    float2 hf = __bfloat1622float2(hb);
    __nv_bfloat162 lb = __floats2bfloat162_rn(a - hf.x, b - hf.y);
    h = *(uint32_t*)&hb;
    l = *(uint32_t*)&lb;
}

__device__ __forceinline__ uint32_t lds32(const __nv_bfloat16* p) {
    return *(const uint32_t*)p;
}

// ---------------------------------------------------------------------------
// bf16x3 GEMM (unchanged from round 3 — validated at rel_err 1e-5)
// ---------------------------------------------------------------------------
constexpr int RS = 20;
constexpr int TILE_U32 = 128 * RS;
constexpr int SM_U32_TOTAL = 8 * TILE_U32;

template <bool HEAD_LAYOUT>
__global__ void __launch_bounds__(256)
bf16x3_gemm(const float* __restrict__ A, const float* __restrict__ W,
            float* __restrict__ C, const float* __restrict__ bias) {
    extern __shared__ uint32_t sm[];
    const int tid = threadIdx.x;
    const int lane = tid & 31;
    const int warp = tid >> 5;
    const int g = lane >> 2;
    const int t = lane & 3;
    const int bm = blockIdx.y * 128;
    const int bn = blockIdx.x * 128;
    const int wm = (warp >> 2) * 64;
    const int wn = (warp & 3) * 32;

    float acc[4][4][4];
#pragma unroll
    for (int mi = 0; mi < 4; mi++)
#pragma unroll
        for (int ni = 0; ni < 4; ni++)
#pragma unroll
            for (int r = 0; r < 4; r++) acc[mi][ni][r] = 0.f;

    float4 ra[4], rb[4];
    const float* Ag = A + (size_t)bm * Dd;
    const float* Wg = W + (size_t)bn * Dd;

#pragma unroll
    for (int i = 0; i < 4; i++) {
        const int c = tid + i * 256;
        const int row = c >> 3, q = c & 7;
        ra[i] = *(const float4*)(Ag + (size_t)row * Dd + q * 4);
        rb[i] = *(const float4*)(Wg + (size_t)row * Dd + q * 4);
    }

    for (int kc = 0; kc < Dd / 32; kc++) {
        const int st = kc & 1;
        uint32_t* sAh = sm + (st * 4 + 0) * TILE_U32;
        uint32_t* sAl = sm + (st * 4 + 1) * TILE_U32;
        uint32_t* sBh = sm + (st * 4 + 2) * TILE_U32;
        uint32_t* sBl = sm + (st * 4 + 3) * TILE_U32;

#pragma unroll
        for (int i = 0; i < 4; i++) {
            const int c = tid + i * 256;
            const int row = c >> 3, q = c & 7;
            const int so = row * RS + q * 2;
            split2(ra[i].x, ra[i].y, sAh[so], sAl[so]);
            split2(ra[i].z, ra[i].w, sAh[so + 1], sAl[so + 1]);
            split2(rb[i].x, rb[i].y, sBh[so], sBl[so]);
            split2(rb[i].z, rb[i].w, sBh[so + 1], sBl[so + 1]);
        }
        __syncthreads();

        if (kc + 1 < Dd / 32) {
            const float* An = Ag + (kc + 1) * 32;
            const float* Wn = Wg + (kc + 1) * 32;
#pragma unroll
            for (int i = 0; i < 4; i++) {
                const int c = tid + i * 256;
                const int row = c >> 3, q = c & 7;
                ra[i] = *(const float4*)(An + (size_t)row * Dd + q * 4);
                rb[i] = *(const float4*)(Wn + (size_t)row * Dd + q * 4);
            }
        }

#pragma unroll
        for (int s = 0; s < 2; s++) {
            const int ko = s * 8;
            uint32_t ah[4][4], al[4][4];
#pragma unroll
            for (int mi = 0; mi < 4; mi++) {
                const int base = (wm + mi * 16 + g) * RS + ko + t;
                ah[mi][0] = sAh[base];
                ah[mi][1] = sAh[base + 8 * RS];
                ah[mi][2] = sAh[base + 4];
                ah[mi][3] = sAh[base + 8 * RS + 4];
                al[mi][0] = sAl[base];
                al[mi][1] = sAl[base + 8 * RS];
                al[mi][2] = sAl[base + 4];
                al[mi][3] = sAl[base + 8 * RS + 4];
            }
            uint32_t bh[4][2], bl[4][2];
#pragma unroll
            for (int ni = 0; ni < 4; ni++) {
                const int base = (wn + ni * 8 + g) * RS + ko + t;
                bh[ni][0] = sBh[base];
                bh[ni][1] = sBh[base + 4];
                bl[ni][0] = sBl[base];
                bl[ni][1] = sBl[base + 4];
            }
#pragma unroll
            for (int mi = 0; mi < 4; mi++)
#pragma unroll
                for (int ni = 0; ni < 4; ni++) {
                    mma_bf16(acc[mi][ni], ah[mi], bh[ni]);
                    mma_bf16(acc[mi][ni], ah[mi], bl[ni]);
                    mma_bf16(acc[mi][ni], al[mi], bh[ni]);
                }
        }
        __syncthreads();
    }

#pragma unroll
    for (int mi = 0; mi < 4; mi++) {
        const int m0 = bm + wm + mi * 16 + g;
#pragma unroll
        for (int ni = 0; ni < 4; ni++) {
            const int n = bn + wn + ni * 8 + 2 * t;
            float c0 = acc[mi][ni][0], c1 = acc[mi][ni][1];
            float c2 = acc[mi][ni][2], c3 = acc[mi][ni][3];
            if (!HEAD_LAYOUT) {
                const float bx = bias[n], by = bias[n + 1];
                *(float2*)(C + (size_t)m0 * Dd + n) = make_float2(c0 + bx, c1 + by);
                *(float2*)(C + (size_t)(m0 + 8) * Dd + n) = make_float2(c2 + bx, c3 + by);
            } else {
                const int h_ = n >> 6, d_ = n & 63;
                {
                    const int b_ = m0 >> 11, t_ = m0 & (Ts - 1);
                    float* p = C + (((size_t)(b_ * Hh + h_) * Ts + t_) << 6) + d_;
                    *(float2*)p = make_float2(c0, c1);
                }
                {
                    const int m1 = m0 + 8;
                    const int b_ = m1 >> 11, t_ = m1 & (Ts - 1);
                    float* p = C + (((size_t)(b_ * Hh + h_) * Ts + t_) << 6) + d_;
                    *(float2*)p = make_float2(c2, c3);
                }
            }
        }
    }
}

// ---------------------------------------------------------------------------
// Flash attention with bf16x3 tensor-core MMAs.
// CTA: 128 queries x one (b,h). Key blocks of 64. 8 warps, each 16 q-rows.
// SMEM (bf16, row stride 72): Qhi/Qlo [128x64], Khi/Klo [64x64] token-major,
// Vthi/Vtlo [64x64] dim-major (transposed). Total 73728 B.
// ---------------------------------------------------------------------------
constexpr int FSTR = 72;
constexpr int F_QH = 0;
constexpr int F_QL = 128 * FSTR;           // 9216
constexpr int F_KH = 2 * 128 * FSTR;       // 18432
constexpr int F_KL = F_KH + 64 * FSTR;     // 23040
constexpr int F_VH = F_KL + 64 * FSTR;     // 27648
constexpr int F_VL = F_VH + 64 * FSTR;     // 32256
constexpr int F_TOTAL_BF16 = F_VL + 64 * FSTR;  // 36864
constexpr int F_SMEM_BYTES = F_TOTAL_BF16 * 2;  // 73728

__global__ void __launch_bounds__(256, 1) flash_mma() {
    extern __shared__ __nv_bfloat16 fsm[];
    const int tid = threadIdx.x;
    const int lane = tid & 31;
    const int w = tid >> 5;
    const int g = lane >> 2;
    const int t = lane & 3;
    const int qb = blockIdx.x;   // 0..15 (128-query blocks)
    const int bh = blockIdx.y;   // 0..63
    const int q0 = qb * 128;

    const float* Qg = g_Q + (size_t)bh * Ts * HD;
    const float* Kg = g_K + (size_t)bh * Ts * HD;
    const float* Vg = g_V + (size_t)bh * Ts * HD;

    // ---- load Q block, scale folded, split hi/lo ----
#pragma unroll
    for (int i = 0; i < 8; i++) {
        const int c = tid + i * 256;
        const int row = c >> 4, q = (c & 15) * 4;
        float4 v = *(const float4*)(Qg + (size_t)(q0 + row) * HD + q);
        v.x *= 0.125f; v.y *= 0.125f; v.z *= 0.125f; v.w *= 0.125f;
        const int so = row * FSTR + q;
        split2(v.x, v.y, *(uint32_t*)&fsm[F_QH + so], *(uint32_t*)&fsm[F_QL + so]);
        split2(v.z, v.w, *(uint32_t*)&fsm[F_QH + so + 2], *(uint32_t*)&fsm[F_QL + so + 2]);
    }
    __syncthreads();

    // ---- Q fragments to registers (reused for all key blocks) ----
    uint32_t qh[4][4], ql[4][4];
    const int rloc = w * 16 + g;   // local query row (0..127)
#pragma unroll
    for (int s = 0; s < 4; s++) {
        const int b0 = rloc * FSTR + 16 * s + 2 * t;
        const int b1 = b0 + 8 * FSTR;
        qh[s][0] = lds32(&fsm[F_QH + b0]);
        qh[s][1] = lds32(&fsm[F_QH + b1]);
        qh[s][2] = lds32(&fsm[F_QH + b0 + 8]);
        qh[s][3] = lds32(&fsm[F_QH + b1 + 8]);
        ql[s][0] = lds32(&fsm[F_QL + b0]);
        ql[s][1] = lds32(&fsm[F_QL + b1]);
        ql[s][2] = lds32(&fsm[F_QL + b0 + 8]);
        ql[s][3] = lds32(&fsm[F_QL + b1 + 8]);
    }

    const int r0 = q0 + rloc;      // global query rows
    const int r1 = r0 + 8;

    float o[8][4];
#pragma unroll
    for (int nb = 0; nb < 8; nb++)
#pragma unroll
        for (int r = 0; r < 4; r++) o[nb][r] = 0.f;
    float m0 = -1e30f, m1 = -1e30f, l0 = 0.f, l1 = 0.f;

    const int nkb = 2 * qb + 2;
    for (int kb = 0; kb < nkb; kb++) {
        const int k0 = kb * 64;
        __syncthreads();  // previous iteration's K/V readers done
        // ---- load K (token-major) and V (transposed, dim-major) ----
#pragma unroll
        for (int i = 0; i < 4; i++) {
            const int c = tid + i * 256;
            const int row = c >> 4, q = (c & 15) * 4;
            float4 kv = *(const float4*)(Kg + (size_t)(k0 + row) * HD + q);
            const int so = row * FSTR + q;
            split2(kv.x, kv.y, *(uint32_t*)&fsm[F_KH + so], *(uint32_t*)&fsm[F_KL + so]);
            split2(kv.z, kv.w, *(uint32_t*)&fsm[F_KH + so + 2], *(uint32_t*)&fsm[F_KL + so + 2]);
            float4 vv = *(const float4*)(Vg + (size_t)(k0 + row) * HD + q);
#pragma unroll
            for (int j = 0; j < 4; j++) {
                const float val = (&vv.x)[j];
                const __nv_bfloat16 hb = __float2bfloat16_rn(val);
                const __nv_bfloat16 lb = __float2bfloat16_rn(val - __bfloat162float(hb));
                fsm[F_VH + (q + j) * FSTR + row] = hb;
                fsm[F_VL + (q + j) * FSTR + row] = lb;
            }
        }
        __syncthreads();

        // ---- S = Q . K^T ----
        float s[8][4];
#pragma unroll
        for (int nb = 0; nb < 8; nb++)
#pragma unroll
            for (int r = 0; r < 4; r++) s[nb][r] = 0.f;
#pragma unroll
        for (int ks = 0; ks < 4; ks++) {
#pragma unroll
            for (int nb = 0; nb < 8; nb++) {
                const int base = (8 * nb + g) * FSTR + 16 * ks + 2 * t;
                uint32_t kh[2], kl[2];
                kh[0] = lds32(&fsm[F_KH + base]);
                kh[1] = lds32(&fsm[F_KH + base + 8]);
                kl[0] = lds32(&fsm[F_KL + base]);
                kl[1] = lds32(&fsm[F_KL + base + 8]);
                mma_bf16(s[nb], qh[ks], kh);
                mma_bf16(s[nb], qh[ks], kl);
                mma_bf16(s[nb], ql[ks], kh);
            }
        }

        // ---- causal mask (only the last two key blocks can clip) ----
        if (kb >= 2 * qb) {
#pragma unroll
            for (int nb = 0; nb < 8; nb++) {
                const int key0 = k0 + 8 * nb + 2 * t;
                if (key0 > r0) s[nb][0] = -1e30f;
                if (key0 + 1 > r0) s[nb][1] = -1e30f;
                if (key0 > r1) s[nb][2] = -1e30f;
                if (key0 + 1 > r1) s[nb][3] = -1e30f;
            }
        }

        // ---- online softmax (warp-local; rows live on 4-lane quads) ----
        float rm0 = -1e30f, rm1 = -1e30f;
#pragma unroll
        for (int nb = 0; nb < 8; nb++) {
            rm0 = fmaxf(rm0, fmaxf(s[nb][0], s[nb][1]));
            rm1 = fmaxf(rm1, fmaxf(s[nb][2], s[nb][3]));
        }
#pragma unroll
        for (int off = 1; off < 4; off <<= 1) {
            rm0 = fmaxf(rm0, __shfl_xor_sync(0xffffffffu, rm0, off));
            rm1 = fmaxf(rm1, __shfl_xor_sync(0xffffffffu, rm1, off));
        }
        const float nm0 = fmaxf(m0, rm0), nm1 = fmaxf(m1, rm1);
        const float corr0 = __expf(m0 - nm0), corr1 = __expf(m1 - nm1);
        m0 = nm0; m1 = nm1;
        float sum0 = 0.f, sum1 = 0.f;
#pragma unroll
        for (int nb = 0; nb < 8; nb++) {
            s[nb][0] = __expf(s[nb][0] - m0);
            s[nb][1] = __expf(s[nb][1] - m0);
            s[nb][2] = __expf(s[nb][2] - m1);
            s[nb][3] = __expf(s[nb][3] - m1);
            sum0 += s[nb][0] + s[nb][1];
            sum1 += s[nb][2] + s[nb][3];
        }
#pragma unroll
        for (int off = 1; off < 4; off <<= 1) {
            sum0 += __shfl_xor_sync(0xffffffffu, sum0, off);
            sum1 += __shfl_xor_sync(0xffffffffu, sum1, off);
        }
        l0 = l0 * corr0 + sum0;
        l1 = l1 * corr1 + sum1;
#pragma unroll
        for (int nb = 0; nb < 8; nb++) {
            o[nb][0] *= corr0;
            o[nb][1] *= corr0;
            o[nb][2] *= corr1;
            o[nb][3] *= corr1;
        }

        // ---- O += P . V (P packed in-register to a-fragments, hi/lo) ----
#pragma unroll
        for (int st = 0; st < 4; st++) {
            uint32_t ph[4], pl[4];
            split2(s[2 * st][0], s[2 * st][1], ph[0], pl[0]);
            split2(s[2 * st][2], s[2 * st][3], ph[1], pl[1]);
            split2(s[2 * st + 1][0], s[2 * st + 1][1], ph[2], pl[2]);
            split2(s[2 * st + 1][2], s[2 * st + 1][3], ph[3], pl[3]);
#pragma unroll
            for (int nb = 0; nb < 8; nb++) {
                const int base = (8 * nb + g) * FSTR + 16 * st + 2 * t;
                uint32_t vh[2], vl[2];
                vh[0] = lds32(&fsm[F_VH + base]);
                vh[1] = lds32(&fsm[F_VH + base + 8]);
                vl[0] = lds32(&fsm[F_VL + base]);
                vl[1] = lds32(&fsm[F_VL + base + 8]);
                mma_bf16(o[nb], ph, vh);
                mma_bf16(o[nb], ph, vl);
                mma_bf16(o[nb], pl, vh);
            }
        }
    }

    // ---- epilogue: normalize, scatter to [B, T, D] ----
    const int b_ = bh >> 4;
    const int h_ = bh & 15;
    const float inv0 = 1.f / l0, inv1 = 1.f / l1;
#pragma unroll
    for (int nb = 0; nb < 8; nb++) {
        const int col = h_ * 64 + 8 * nb + 2 * t;
        *(float2*)(g_attn + ((size_t)(b_ * Ts + r0)) * Dd + col) =
            make_float2(o[nb][0] * inv0, o[nb][1] * inv0);
        *(float2*)(g_attn + ((size_t)(b_ * Ts + r1)) * Dd + col) =
            make_float2(o[nb][2] * inv1, o[nb][3] * inv1);
    }
}

// ---------------------------------------------------------------------------
extern "C" void kernel_launch(void* const* d_in, const int* in_sizes, int n_in,
                              void* d_out, int out_size) {
    const float* xq = (const float*)d_in[0];
    const float* xk = (const float*)d_in[1];
    const float* xv = (const float*)d_in[2];
    const float* Wq = (const float*)d_in[3];
    const float* Wk = (const float*)d_in[4];
    const float* Wv = (const float*)d_in[5];
    const float* Wo = (const float*)d_in[6];
    const float* bo = (const float*)d_in[7];
    float* out = (float*)d_out;

    float *gq, *gk, *gv, *ga;
    cudaGetSymbolAddress((void**)&gq, g_Q);
    cudaGetSymbolAddress((void**)&gk, g_K);
    cudaGetSymbolAddress((void**)&gv, g_V);
    cudaGetSymbolAddress((void**)&ga, g_attn);

    const int gemm_smem = SM_U32_TOTAL * 4;  // 81920
    cudaFuncSetAttribute(bf16x3_gemm<true>,
                         cudaFuncAttributeMaxDynamicSharedMemorySize, gemm_smem);
    cudaFuncSetAttribute(bf16x3_gemm<false>,
                         cudaFuncAttributeMaxDynamicSharedMemorySize, gemm_smem);
    cudaFuncSetAttribute(flash_mma,
                         cudaFuncAttributeMaxDynamicSharedMemorySize, F_SMEM_BYTES);

    dim3 grid(Dd / 128, Mrows / 128);  // (8, 64)
    bf16x3_gemm<true><<<grid, 256, gemm_smem>>>(xq, Wq, gq, nullptr);
    bf16x3_gemm<true><<<grid, 256, gemm_smem>>>(xk, Wk, gk, nullptr);
    bf16x3_gemm<true><<<grid, 256, gemm_smem>>>(xv, Wv, gv, nullptr);
    flash_mma<<<dim3(Ts / 128, Bb * Hh), 256, F_SMEM_BYTES>>>();
    bf16x3_gemm<false><<<grid, 256, gemm_smem>>>(ga, Wo, out, bo);
}

// round 5
// speedup vs baseline: 2.8210x; 1.1299x over previous
#include <cuda_runtime.h>
#include <cuda_bf16.h>
#include <cstdint>

// Fixed problem shape
constexpr int Bb = 4;
constexpr int Ts = 2048;
constexpr int Dd = 1024;
constexpr int Hh = 16;
constexpr int HD = 64;
constexpr int Mrows = Bb * Ts;               // 8192
constexpr size_t XSZ = (size_t)Mrows * Dd;   // 8388608
constexpr size_t WSZ = (size_t)Dd * Dd;      // 1048576

// ---------------------------------------------------------------------------
// Device scratch: everything bf16 hi/lo after the prep pass.
// ---------------------------------------------------------------------------
__device__ __nv_bfloat16 g_Xh[3][XSZ], g_Xl[3][XSZ];   // split inputs (q,k,v)
__device__ __nv_bfloat16 g_Wh[4][WSZ], g_Wl[4][WSZ];   // split weights (q,k,v,o)
__device__ __nv_bfloat16 g_Ph[3][XSZ], g_Pl[3][XSZ];   // projected Q,K,V (head layout)
__device__ __nv_bfloat16 g_Ah[XSZ], g_Al[XSZ];         // attention output [8192,1024]

// ---------------------------------------------------------------------------
// Helpers
// ---------------------------------------------------------------------------
__device__ __forceinline__ void mma_bf16(float* d, const uint32_t* a, const uint32_t* b) {
    asm volatile(
        "mma.sync.aligned.m16n8k16.row.col.f32.bf16.bf16.f32 "
        "{%0,%1,%2,%3}, {%4,%5,%6,%7}, {%8,%9}, {%0,%1,%2,%3};"
        : "+f"(d[0]), "+f"(d[1]), "+f"(d[2]), "+f"(d[3])
        : "r"(a[0]), "r"(a[1]), "r"(a[2]), "r"(a[3]), "r"(b[0]), "r"(b[1]));
}
__device__ __forceinline__ void split2(float a, float b, uint32_t& h, uint32_t& l) {
    __nv_bfloat162 hb = __floats2bfloat162_rn(a, b);
    float2 hf = __bfloat1622float2(hb);
    __nv_bfloat162 lb = __floats2bfloat162_rn(a - hf.x, b - hf.y);
    h = *(uint32_t*)&hb;
    l = *(uint32_t*)&lb;
}
__device__ __forceinline__ uint32_t smem_u32(const void* p) {
    uint32_t a;
    asm("{ .reg .u64 t; cvta.to.shared.u64 t, %1; cvt.u32.u64 %0, t; }" : "=r"(a) : "l"(p));
    return a;
}
__device__ __forceinline__ void ldmx4(uint32_t* r, uint32_t addr) {
    asm volatile("ldmatrix.sync.aligned.m8n8.x4.shared.b16 {%0,%1,%2,%3}, [%4];"
                 : "=r"(r[0]), "=r"(r[1]), "=r"(r[2]), "=r"(r[3]) : "r"(addr));
}
__device__ __forceinline__ void ldmx4t(uint32_t* r, uint32_t addr) {
    asm volatile("ldmatrix.sync.aligned.m8n8.x4.trans.shared.b16 {%0,%1,%2,%3}, [%4];"
                 : "=r"(r[0]), "=r"(r[1]), "=r"(r[2]), "=r"(r[3]) : "r"(addr));
}

// ---------------------------------------------------------------------------
// Prep: fp32 -> (hi, lo) bf16 split, optional scale.
// ---------------------------------------------------------------------------
__global__ void cvt_split(const float4* __restrict__ in, uint2* __restrict__ oh,
                          uint2* __restrict__ ol, int n4, float scale) {
    const int i = blockIdx.x * blockDim.x + threadIdx.x;
    if (i >= n4) return;
    float4 v = in[i];
    v.x *= scale; v.y *= scale; v.z *= scale; v.w *= scale;
    uint32_t h01, l01, h23, l23;
    split2(v.x, v.y, h01, l01);
    split2(v.z, v.w, h23, l23);
    oh[i] = make_uint2(h01, h23);
    ol[i] = make_uint2(l01, l23);
}

// ---------------------------------------------------------------------------
// bf16x3 GEMM on pre-split inputs. C = A @ B^T, M=8192, N=K=1024.
// 128x128 tile, BK=32, 256 threads, 8 warps (2m x 4n), ldmatrix fragments.
// MODE 0: write split bf16 output in head layout. MODE 1: fp32 + bias.
// ---------------------------------------------------------------------------
constexpr int RS = 20;                 // padded row stride (u32): 16 data + 4 pad
constexpr int TILE_U32 = 128 * RS;     // 2560
constexpr int GEMM_SMEM = 8 * TILE_U32 * 4;  // 81920 B

template <int MODE>
__device__ __forceinline__ void gemm_core(
    const __nv_bfloat16* __restrict__ Ah, const __nv_bfloat16* __restrict__ Al,
    const __nv_bfloat16* __restrict__ Bh, const __nv_bfloat16* __restrict__ Bl,
    uint32_t* __restrict__ Ch, uint32_t* __restrict__ Cl,
    float* __restrict__ C, const float* __restrict__ bias) {
    extern __shared__ uint32_t sm[];
    const uint32_t smb = smem_u32(sm);
    const int tid = threadIdx.x, lane = tid & 31, warp = tid >> 5;
    const int bm = blockIdx.y * 128, bn = blockIdx.x * 128;
    const int wm = (warp >> 2) * 64, wn = (warp & 3) * 32;
    const int row_off = lane & 7, sel = lane >> 3;
    const uint32_t aoff = ((uint32_t)(row_off + 8 * (sel & 1)) * RS + (sel >> 1) * 4) * 4;
    const uint32_t boff = ((uint32_t)(row_off + 8 * (sel >> 1)) * RS + (sel & 1) * 4) * 4;
    const int lrow = tid >> 2, lch = tid & 3;

    float acc[4][4][4];
#pragma unroll
    for (int mi = 0; mi < 4; mi++)
#pragma unroll
        for (int ni = 0; ni < 4; ni++)
#pragma unroll
            for (int r = 0; r < 4; r++) acc[mi][ni][r] = 0.f;

    uint4 rah[2], ral[2], rbh[2], rbl[2];
#pragma unroll
    for (int i = 0; i < 2; i++) {
        const size_t ao = (size_t)(bm + lrow + i * 64) * Dd + lch * 8;
        rah[i] = *(const uint4*)(Ah + ao);
        ral[i] = *(const uint4*)(Al + ao);
        const size_t bo = (size_t)(bn + lrow + i * 64) * Dd + lch * 8;
        rbh[i] = *(const uint4*)(Bh + bo);
        rbl[i] = *(const uint4*)(Bl + bo);
    }

    for (int kc = 0; kc < Dd / 32; kc++) {
        const int st = kc & 1;
        uint32_t* sAh = sm + (st * 4 + 0) * TILE_U32;
        uint32_t* sAl = sm + (st * 4 + 1) * TILE_U32;
        uint32_t* sBh = sm + (st * 4 + 2) * TILE_U32;
        uint32_t* sBl = sm + (st * 4 + 3) * TILE_U32;
#pragma unroll
        for (int i = 0; i < 2; i++) {
            const int off = (lrow + i * 64) * RS + lch * 4;
            *(uint4*)(sAh + off) = rah[i];
            *(uint4*)(sAl + off) = ral[i];
            *(uint4*)(sBh + off) = rbh[i];
            *(uint4*)(sBl + off) = rbl[i];
        }
        __syncthreads();
        if (kc + 1 < Dd / 32) {
#pragma unroll
            for (int i = 0; i < 2; i++) {
                const size_t ao = (size_t)(bm + lrow + i * 64) * Dd + (kc + 1) * 32 + lch * 8;
                rah[i] = *(const uint4*)(Ah + ao);
                ral[i] = *(const uint4*)(Al + ao);
                const size_t bo = (size_t)(bn + lrow + i * 64) * Dd + (kc + 1) * 32 + lch * 8;
                rbh[i] = *(const uint4*)(Bh + bo);
                rbl[i] = *(const uint4*)(Bl + bo);
            }
        }
        const uint32_t bAh = smb + (st * 4 + 0) * TILE_U32 * 4;
        const uint32_t bAl = smb + (st * 4 + 1) * TILE_U32 * 4;
        const uint32_t bBh = smb + (st * 4 + 2) * TILE_U32 * 4;
        const uint32_t bBl = smb + (st * 4 + 3) * TILE_U32 * 4;
#pragma unroll
        for (int ks = 0; ks < 2; ks++) {
            uint32_t ah[4][4], al[4][4], bh[4][2], bl[4][2];
#pragma unroll
            for (int mi = 0; mi < 4; mi++) {
                const uint32_t ad = (uint32_t)((wm + mi * 16) * RS + ks * 8) * 4;
                ldmx4(ah[mi], bAh + ad + aoff);
                ldmx4(al[mi], bAl + ad + aoff);
            }
#pragma unroll
            for (int np = 0; np < 2; np++) {
                const uint32_t bd = (uint32_t)((wn + np * 16) * RS + ks * 8) * 4;
                uint32_t t4[4];
                ldmx4(t4, bBh + bd + boff);
                bh[2 * np][0] = t4[0]; bh[2 * np][1] = t4[1];
                bh[2 * np + 1][0] = t4[2]; bh[2 * np + 1][1] = t4[3];
                ldmx4(t4, bBl + bd + boff);
                bl[2 * np][0] = t4[0]; bl[2 * np][1] = t4[1];
                bl[2 * np + 1][0] = t4[2]; bl[2 * np + 1][1] = t4[3];
            }
#pragma unroll
            for (int mi = 0; mi < 4; mi++)
#pragma unroll
                for (int ni = 0; ni < 4; ni++) {
                    mma_bf16(acc[mi][ni], ah[mi], bh[ni]);
                    mma_bf16(acc[mi][ni], ah[mi], bl[ni]);
                    mma_bf16(acc[mi][ni], al[mi], bh[ni]);
                }
        }
        __syncthreads();
    }

    const int g = lane >> 2, t = lane & 3;
#pragma unroll
    for (int mi = 0; mi < 4; mi++) {
        const int m0 = bm + wm + mi * 16 + g;
#pragma unroll
        for (int ni = 0; ni < 4; ni++) {
            const int n = bn + wn + ni * 8 + 2 * t;
            const float c0 = acc[mi][ni][0], c1 = acc[mi][ni][1];
            const float c2 = acc[mi][ni][2], c3 = acc[mi][ni][3];
            if (MODE == 1) {
                const float bx = bias[n], by = bias[n + 1];
                *(float2*)(C + (size_t)m0 * Dd + n) = make_float2(c0 + bx, c1 + by);
                *(float2*)(C + (size_t)(m0 + 8) * Dd + n) = make_float2(c2 + bx, c3 + by);
            } else {
                const int h_ = n >> 6, d_ = n & 63;
                uint32_t h01, l01;
                {
                    split2(c0, c1, h01, l01);
                    const int b_ = m0 >> 11, t_ = m0 & (Ts - 1);
                    const size_t idx =
                        (((((size_t)(b_ * Hh + h_) * Ts + t_) << 6) + d_) >> 1);
                    Ch[idx] = h01; Cl[idx] = l01;
                }
                {
                    split2(c2, c3, h01, l01);
                    const int m1 = m0 + 8;
                    const int b_ = m1 >> 11, t_ = m1 & (Ts - 1);
                    const size_t idx =
                        (((((size_t)(b_ * Hh + h_) * Ts + t_) << 6) + d_) >> 1);
                    Ch[idx] = h01; Cl[idx] = l01;
                }
            }
        }
    }
}

__global__ void __launch_bounds__(256) gemm_qkv() {
    const int z = blockIdx.z;
    gemm_core<0>(g_Xh[z], g_Xl[z], g_Wh[z], g_Wl[z],
                 (uint32_t*)g_Ph[z], (uint32_t*)g_Pl[z], nullptr, nullptr);
}
__global__ void __launch_bounds__(256) gemm_out(float* C, const float* bias) {
    gemm_core<1>(g_Ah, g_Al, g_Wh[3], g_Wl[3], nullptr, nullptr, C, bias);
}

// ---------------------------------------------------------------------------
// Flash attention, bf16x3 MMA, pre-split inputs, ldmatrix fragments.
// CTA: 128 queries x one (b,h); key blocks of 64; 8 warps x 16 q-rows.
// SMEM bf16 (stride 72): Qh/Ql[128x64], Kh/Kl[64x64], Vh/Vl[64x64] token-major.
// ---------------------------------------------------------------------------
constexpr int FSTR = 72;
constexpr int F_QH = 0;
constexpr int F_QL = 128 * FSTR;
constexpr int F_KH = 2 * 128 * FSTR;
constexpr int F_KL = F_KH + 64 * FSTR;
constexpr int F_VH = F_KL + 64 * FSTR;
constexpr int F_VL = F_VH + 64 * FSTR;
constexpr int F_SMEM_BYTES = (F_VL + 64 * FSTR) * 2;  // 73728

__global__ void __launch_bounds__(256, 1) flash_mma() {
    extern __shared__ __nv_bfloat16 fsm[];
    const uint32_t smb = smem_u32(fsm);
    const int tid = threadIdx.x;
    const int lane = tid & 31;
    const int w = tid >> 5;
    const int g = lane >> 2;
    const int t = lane & 3;
    const int qb = blockIdx.x;
    const int bh = blockIdx.y;
    const int q0 = qb * 128;

    const int row_off = lane & 7, sel = lane >> 3;
    // a-frag / v-trans offset (rows from sel&1, cols from sel>>1)
    const uint32_t aoffF = ((uint32_t)(row_off + 8 * (sel & 1)) * 36 + (sel >> 1) * 4) * 4;
    // b-frag offset (rows from sel>>1, k-part from sel&1)
    const uint32_t boffF = ((uint32_t)(row_off + 8 * (sel >> 1)) * 36 + (sel & 1) * 4) * 4;

    const __nv_bfloat16* Qh = g_Ph[0] + (size_t)bh * Ts * HD;
    const __nv_bfloat16* Ql = g_Pl[0] + (size_t)bh * Ts * HD;
    const __nv_bfloat16* Kh = g_Ph[1] + (size_t)bh * Ts * HD;
    const __nv_bfloat16* Kl = g_Pl[1] + (size_t)bh * Ts * HD;
    const __nv_bfloat16* Vh = g_Ph[2] + (size_t)bh * Ts * HD;
    const __nv_bfloat16* Vl = g_Pl[2] + (size_t)bh * Ts * HD;

    // ---- load Q (already scaled via Wq prep) ----
#pragma unroll
    for (int i = 0; i < 4; i++) {
        const int c = tid + i * 256;
        const int row = c >> 3, ch = c & 7;
        const size_t go = (size_t)(q0 + row) * HD + ch * 8;
        *(uint4*)(fsm + F_QH + row * FSTR + ch * 8) = *(const uint4*)(Qh + go);
        *(uint4*)(fsm + F_QL + row * FSTR + ch * 8) = *(const uint4*)(Ql + go);
    }
    __syncthreads();

    // ---- Q fragments (persist across key blocks) ----
    uint32_t qh[4][4], ql[4][4];
#pragma unroll
    for (int ks = 0; ks < 4; ks++) {
        const uint32_t qd = (uint32_t)((w * 16) * 36 + ks * 8) * 4;
        ldmx4(qh[ks], smb + F_QH * 2 + qd + aoffF);
        ldmx4(ql[ks], smb + F_QL * 2 + qd + aoffF);
    }

    const int r0 = q0 + w * 16 + g;
    const int r1 = r0 + 8;

    float o[8][4];
#pragma unroll
    for (int nb = 0; nb < 8; nb++)
#pragma unroll
        for (int r = 0; r < 4; r++) o[nb][r] = 0.f;
    float m0 = -1e30f, m1 = -1e30f, l0 = 0.f, l1 = 0.f;

    const int nkb = 2 * qb + 2;
    for (int kb = 0; kb < nkb; kb++) {
        const int k0 = kb * 64;
        __syncthreads();
#pragma unroll
        for (int i = 0; i < 2; i++) {
            const int c = tid + i * 256;
            const int row = c >> 3, ch = c & 7;
            const size_t go = (size_t)(k0 + row) * HD + ch * 8;
            const int so = row * FSTR + ch * 8;
            *(uint4*)(fsm + F_KH + so) = *(const uint4*)(Kh + go);
            *(uint4*)(fsm + F_KL + so) = *(const uint4*)(Kl + go);
            *(uint4*)(fsm + F_VH + so) = *(const uint4*)(Vh + go);
            *(uint4*)(fsm + F_VL + so) = *(const uint4*)(Vl + go);
        }
        __syncthreads();

        // ---- S = Q . K^T ----
        float s[8][4];
#pragma unroll
        for (int nb = 0; nb < 8; nb++)
#pragma unroll
            for (int r = 0; r < 4; r++) s[nb][r] = 0.f;
#pragma unroll
        for (int ks = 0; ks < 4; ks++) {
#pragma unroll
            for (int np = 0; np < 4; np++) {
                const uint32_t kd = (uint32_t)((np * 16) * 36 + ks * 8) * 4;
                uint32_t kh4[4], kl4[4];
                ldmx4(kh4, smb + F_KH * 2 + kd + boffF);
                ldmx4(kl4, smb + F_KL * 2 + kd + boffF);
                mma_bf16(s[2 * np], qh[ks], kh4);
                mma_bf16(s[2 * np], qh[ks], kl4);
                mma_bf16(s[2 * np], ql[ks], kh4);
                mma_bf16(s[2 * np + 1], qh[ks], kh4 + 2);
                mma_bf16(s[2 * np + 1], qh[ks], kl4 + 2);
                mma_bf16(s[2 * np + 1], ql[ks], kh4 + 2);
            }
        }

        // ---- causal mask (only last two key blocks clip) ----
        if (kb >= 2 * qb) {
#pragma unroll
            for (int nb = 0; nb < 8; nb++) {
                const int key0 = k0 + 8 * nb + 2 * t;
                if (key0 > r0) s[nb][0] = -1e30f;
                if (key0 + 1 > r0) s[nb][1] = -1e30f;
                if (key0 > r1) s[nb][2] = -1e30f;
                if (key0 + 1 > r1) s[nb][3] = -1e30f;
            }
        }

        // ---- online softmax (quad-local) ----
        float rm0 = -1e30f, rm1 = -1e30f;
#pragma unroll
        for (int nb = 0; nb < 8; nb++) {
            rm0 = fmaxf(rm0, fmaxf(s[nb][0], s[nb][1]));
            rm1 = fmaxf(rm1, fmaxf(s[nb][2], s[nb][3]));
        }
#pragma unroll
        for (int off = 1; off < 4; off <<= 1) {
            rm0 = fmaxf(rm0, __shfl_xor_sync(0xffffffffu, rm0, off));
            rm1 = fmaxf(rm1, __shfl_xor_sync(0xffffffffu, rm1, off));
        }
        const float nm0 = fmaxf(m0, rm0), nm1 = fmaxf(m1, rm1);
        const float corr0 = __expf(m0 - nm0), corr1 = __expf(m1 - nm1);
        m0 = nm0; m1 = nm1;
        float sum0 = 0.f, sum1 = 0.f;
#pragma unroll
        for (int nb = 0; nb < 8; nb++) {
            s[nb][0] = __expf(s[nb][0] - m0);
            s[nb][1] = __expf(s[nb][1] - m0);
            s[nb][2] = __expf(s[nb][2] - m1);
            s[nb][3] = __expf(s[nb][3] - m1);
            sum0 += s[nb][0] + s[nb][1];
            sum1 += s[nb][2] + s[nb][3];
        }
#pragma unroll
        for (int off = 1; off < 4; off <<= 1) {
            sum0 += __shfl_xor_sync(0xffffffffu, sum0, off);
            sum1 += __shfl_xor_sync(0xffffffffu, sum1, off);
        }
        l0 = l0 * corr0 + sum0;
        l1 = l1 * corr1 + sum1;
#pragma unroll
        for (int nb = 0; nb < 8; nb++) {
            o[nb][0] *= corr0;
            o[nb][1] *= corr0;
            o[nb][2] *= corr1;
            o[nb][3] *= corr1;
        }

        // ---- O += P . V (V frags via ldmatrix.trans on token-major tile) ----
#pragma unroll
        for (int st = 0; st < 4; st++) {
            uint32_t ph[4], pl[4];
            split2(s[2 * st][0], s[2 * st][1], ph[0], pl[0]);
            split2(s[2 * st][2], s[2 * st][3], ph[1], pl[1]);
            split2(s[2 * st + 1][0], s[2 * st + 1][1], ph[2], pl[2]);
            split2(s[2 * st + 1][2], s[2 * st + 1][3], ph[3], pl[3]);
#pragma unroll
            for (int p = 0; p < 4; p++) {
                const uint32_t vd = (uint32_t)((16 * st) * 36 + p * 8) * 4;
                uint32_t vh4[4], vl4[4];
                ldmx4t(vh4, smb + F_VH * 2 + vd + aoffF);
                ldmx4t(vl4, smb + F_VL * 2 + vd + aoffF);
                mma_bf16(o[2 * p], ph, vh4);
                mma_bf16(o[2 * p], ph, vl4);
                mma_bf16(o[2 * p], pl, vh4);
                mma_bf16(o[2 * p + 1], ph, vh4 + 2);
                mma_bf16(o[2 * p + 1], ph, vl4 + 2);
                mma_bf16(o[2 * p + 1], pl, vh4 + 2);
            }
        }
    }

    // ---- epilogue: normalize + split to bf16 hi/lo attn buffer ----
    const int b_ = bh >> 4;
    const int h_ = bh & 15;
    const float inv0 = 1.f / l0, inv1 = 1.f / l1;
    uint32_t* gAh = (uint32_t*)g_Ah;
    uint32_t* gAl = (uint32_t*)g_Al;
#pragma unroll
    for (int nb = 0; nb < 8; nb++) {
        const int col = h_ * 64 + 8 * nb + 2 * t;
        uint32_t h01, l01;
        split2(o[nb][0] * inv0, o[nb][1] * inv0, h01, l01);
        size_t idx = (((size_t)(b_ * Ts + r0)) * Dd + col) >> 1;
        gAh[idx] = h01; gAl[idx] = l01;
        split2(o[nb][2] * inv1, o[nb][3] * inv1, h01, l01);
        idx = (((size_t)(b_ * Ts + r1)) * Dd + col) >> 1;
        gAh[idx] = h01; gAl[idx] = l01;
    }
}

// ---------------------------------------------------------------------------
extern "C" void kernel_launch(void* const* d_in, const int* in_sizes, int n_in,
                              void* d_out, int out_size) {
    const float* xin[3] = {(const float*)d_in[0], (const float*)d_in[1],
                           (const float*)d_in[2]};
    const float* win[4] = {(const float*)d_in[3], (const float*)d_in[4],
                           (const float*)d_in[5], (const float*)d_in[6]};
    const float* bo = (const float*)d_in[7];
    float* out = (float*)d_out;

    __nv_bfloat16 *pXh, *pXl, *pWh, *pWl;
    cudaGetSymbolAddress((void**)&pXh, g_Xh);
    cudaGetSymbolAddress((void**)&pXl, g_Xl);
    cudaGetSymbolAddress((void**)&pWh, g_Wh);
    cudaGetSymbolAddress((void**)&pWl, g_Wl);

    cudaFuncSetAttribute(gemm_qkv, cudaFuncAttributeMaxDynamicSharedMemorySize, GEMM_SMEM);
    cudaFuncSetAttribute(gemm_out, cudaFuncAttributeMaxDynamicSharedMemorySize, GEMM_SMEM);
    cudaFuncSetAttribute(flash_mma, cudaFuncAttributeMaxDynamicSharedMemorySize, F_SMEM_BYTES);

    // prep: split inputs and weights (Wq gets softmax scale folded in)
    for (int z = 0; z < 3; z++)
        cvt_split<<<(int)(XSZ / 4 / 256), 256>>>(
            (const float4*)xin[z], (uint2*)(pXh + z * XSZ), (uint2*)(pXl + z * XSZ),
            (int)(XSZ / 4), 1.f);
    for (int z = 0; z < 4; z++)
        cvt_split<<<(int)(WSZ / 4 / 256), 256>>>(
            (const float4*)win[z], (uint2*)(pWh + z * WSZ), (uint2*)(pWl + z * WSZ),
            (int)(WSZ / 4), z == 0 ? 0.125f : 1.f);

    gemm_qkv<<<dim3(Dd / 128, Mrows / 128, 3), 256, GEMM_SMEM>>>();
    flash_mma<<<dim3(Ts / 128, Bb * Hh), 256, F_SMEM_BYTES>>>();
    gemm_out<<<dim3(Dd / 128, Mrows / 128), 256, GEMM_SMEM>>>(out, bo);
}

// round 7
// speedup vs baseline: 3.1238x; 1.1073x over previous
#include <cuda_runtime.h>
#include <cuda_bf16.h>
#include <cstdint>

// Fixed problem shape
constexpr int Bb = 4;
constexpr int Ts = 2048;
constexpr int Dd = 1024;
constexpr int Hh = 16;
constexpr int HD = 64;
constexpr int Mrows = Bb * Ts;               // 8192
constexpr size_t XSZ = (size_t)Mrows * Dd;   // 8388608
constexpr size_t WSZ = (size_t)Dd * Dd;      // 1048576

// Device scratch: everything bf16 hi/lo after the prep pass.
__device__ __nv_bfloat16 g_Xh[3][XSZ], g_Xl[3][XSZ];
__device__ __nv_bfloat16 g_Wh[4][WSZ], g_Wl[4][WSZ];
__device__ __nv_bfloat16 g_Ph[3][XSZ], g_Pl[3][XSZ];
__device__ __nv_bfloat16 g_Ah[XSZ], g_Al[XSZ];

// ---------------------------------------------------------------------------
// Helpers
// ---------------------------------------------------------------------------
__device__ __forceinline__ void mma_bf16(float* d, const uint32_t* a, const uint32_t* b) {
    asm volatile(
        "mma.sync.aligned.m16n8k16.row.col.f32.bf16.bf16.f32 "
        "{%0,%1,%2,%3}, {%4,%5,%6,%7}, {%8,%9}, {%0,%1,%2,%3};"
        : "+f"(d[0]), "+f"(d[1]), "+f"(d[2]), "+f"(d[3])
        : "r"(a[0]), "r"(a[1]), "r"(a[2]), "r"(a[3]), "r"(b[0]), "r"(b[1]));
}
__device__ __forceinline__ void split2(float a, float b, uint32_t& h, uint32_t& l) {
    __nv_bfloat162 hb = __floats2bfloat162_rn(a, b);
    float2 hf = __bfloat1622float2(hb);
    __nv_bfloat162 lb = __floats2bfloat162_rn(a - hf.x, b - hf.y);
    h = *(uint32_t*)&hb;
    l = *(uint32_t*)&lb;
}
__device__ __forceinline__ uint32_t smem_u32(const void* p) {
    uint32_t a;
    asm("{ .reg .u64 t; cvta.to.shared.u64 t, %1; cvt.u32.u64 %0, t; }" : "=r"(a) : "l"(p));
    return a;
}
__device__ __forceinline__ void ldmx4(uint32_t* r, uint32_t addr) {
    asm volatile("ldmatrix.sync.aligned.m8n8.x4.shared.b16 {%0,%1,%2,%3}, [%4];"
                 : "=r"(r[0]), "=r"(r[1]), "=r"(r[2]), "=r"(r[3]) : "r"(addr));
}
__device__ __forceinline__ void ldmx4t(uint32_t* r, uint32_t addr) {
    asm volatile("ldmatrix.sync.aligned.m8n8.x4.trans.shared.b16 {%0,%1,%2,%3}, [%4];"
                 : "=r"(r[0]), "=r"(r[1]), "=r"(r[2]), "=r"(r[3]) : "r"(addr));
}
__device__ __forceinline__ void cpasync16(uint32_t dst, const void* src) {
    asm volatile("cp.async.cg.shared.global [%0], [%1], 16;" ::"r"(dst), "l"(src));
}
#define CP_COMMIT() asm volatile("cp.async.commit_group;" ::: "memory")
#define CP_WAIT(n) asm volatile("cp.async.wait_group %0;" ::"n"(n) : "memory")

// ---------------------------------------------------------------------------
// Prep: fp32 -> (hi, lo) bf16 split, optional scale.
// ---------------------------------------------------------------------------
__global__ void cvt_split(const float4* __restrict__ in, uint2* __restrict__ oh,
                          uint2* __restrict__ ol, int n4, float scale) {
    const int i = blockIdx.x * blockDim.x + threadIdx.x;
    if (i >= n4) return;
    float4 v = in[i];
    v.x *= scale; v.y *= scale; v.z *= scale; v.w *= scale;
    uint32_t h01, l01, h23, l23;
    split2(v.x, v.y, h01, l01);
    split2(v.z, v.w, h23, l23);
    oh[i] = make_uint2(h01, h23);
    ol[i] = make_uint2(l01, l23);
}

// ---------------------------------------------------------------------------
// bf16x3 GEMM, cp.async double-buffered. C = A @ B^T, M=8192, N=K=1024.
// 128x128 tile, BK=32, 256 threads, 8 warps (2m x 4n), ldmatrix fragments.
// ---------------------------------------------------------------------------
constexpr int RS = 20;                 // padded row stride (u32)
constexpr int TILE_U32 = 128 * RS;
constexpr int GEMM_SMEM = 8 * TILE_U32 * 4;  // 81920 B

template <int MODE>
__device__ __forceinline__ void gemm_core(
    const __nv_bfloat16* __restrict__ Ah, const __nv_bfloat16* __restrict__ Al,
    const __nv_bfloat16* __restrict__ Bh, const __nv_bfloat16* __restrict__ Bl,
    uint32_t* __restrict__ Ch, uint32_t* __restrict__ Cl,
    float* __restrict__ C, const float* __restrict__ bias) {
    extern __shared__ uint32_t sm[];
    const uint32_t smb = smem_u32(sm);
    const int tid = threadIdx.x, lane = tid & 31, warp = tid >> 5;
    const int bm = blockIdx.y * 128, bn = blockIdx.x * 128;
    const int wm = (warp >> 2) * 64, wn = (warp & 3) * 32;
    const int row_off = lane & 7, sel = lane >> 3;
    const uint32_t aoff = ((uint32_t)(row_off + 8 * (sel & 1)) * RS + (sel >> 1) * 4) * 4;
    const uint32_t boff = ((uint32_t)(row_off + 8 * (sel >> 1)) * RS + (sel & 1) * 4) * 4;
    const int lrow = tid >> 2, lch = tid & 3;   // loader: 64 rows/pass, 4x16B chunks

    float acc[4][4][4];
#pragma unroll
    for (int mi = 0; mi < 4; mi++)
#pragma unroll
        for (int ni = 0; ni < 4; ni++)
#pragma unroll
            for (int r = 0; r < 4; r++) acc[mi][ni][r] = 0.f;

    auto issue = [&](int kc, int st) {
        const uint32_t base = smb + (uint32_t)st * 4 * TILE_U32 * 4;
#pragma unroll
        for (int i = 0; i < 2; i++) {
            const int row = lrow + i * 64;
            const uint32_t doff = (uint32_t)(row * RS + lch * 4) * 4;
            const size_t asrc = (size_t)(bm + row) * Dd + kc * 32 + lch * 8;
            const size_t bsrc = (size_t)(bn + row) * Dd + kc * 32 + lch * 8;
            cpasync16(base + 0 * TILE_U32 * 4 + doff, Ah + asrc);
            cpasync16(base + 1 * TILE_U32 * 4 + doff, Al + asrc);
            cpasync16(base + 2 * TILE_U32 * 4 + doff, Bh + bsrc);
            cpasync16(base + 3 * TILE_U32 * 4 + doff, Bl + bsrc);
        }
    };

    issue(0, 0);
    CP_COMMIT();

    for (int kc = 0; kc < Dd / 32; kc++) {
        const int st = kc & 1;
        if (kc + 1 < Dd / 32) {
            issue(kc + 1, st ^ 1);
            CP_COMMIT();
            CP_WAIT(1);
        } else {
            CP_WAIT(0);
        }
        __syncthreads();

        const uint32_t bAh = smb + (st * 4 + 0) * TILE_U32 * 4;
        const uint32_t bAl = smb + (st * 4 + 1) * TILE_U32 * 4;
        const uint32_t bBh = smb + (st * 4 + 2) * TILE_U32 * 4;
        const uint32_t bBl = smb + (st * 4 + 3) * TILE_U32 * 4;
#pragma unroll
        for (int ks = 0; ks < 2; ks++) {
            uint32_t ah[4][4], al[4][4], bh[4][2], bl[4][2];
#pragma unroll
            for (int mi = 0; mi < 4; mi++) {
                const uint32_t ad = (uint32_t)((wm + mi * 16) * RS + ks * 8) * 4;
                ldmx4(ah[mi], bAh + ad + aoff);
                ldmx4(al[mi], bAl + ad + aoff);
            }
#pragma unroll
            for (int np = 0; np < 2; np++) {
                const uint32_t bd = (uint32_t)((wn + np * 16) * RS + ks * 8) * 4;
                uint32_t t4[4];
                ldmx4(t4, bBh + bd + boff);
                bh[2 * np][0] = t4[0]; bh[2 * np][1] = t4[1];
                bh[2 * np + 1][0] = t4[2]; bh[2 * np + 1][1] = t4[3];
                ldmx4(t4, bBl + bd + boff);
                bl[2 * np][0] = t4[0]; bl[2 * np][1] = t4[1];
                bl[2 * np + 1][0] = t4[2]; bl[2 * np + 1][1] = t4[3];
            }
#pragma unroll
            for (int mi = 0; mi < 4; mi++)
#pragma unroll
                for (int ni = 0; ni < 4; ni++) {
                    mma_bf16(acc[mi][ni], ah[mi], bh[ni]);
                    mma_bf16(acc[mi][ni], ah[mi], bl[ni]);
                    mma_bf16(acc[mi][ni], al[mi], bh[ni]);
                }
        }
        __syncthreads();
    }

    const int g = lane >> 2, t = lane & 3;
#pragma unroll
    for (int mi = 0; mi < 4; mi++) {
        const int m0 = bm + wm + mi * 16 + g;
#pragma unroll
        for (int ni = 0; ni < 4; ni++) {
            const int n = bn + wn + ni * 8 + 2 * t;
            const float c0 = acc[mi][ni][0], c1 = acc[mi][ni][1];
            const float c2 = acc[mi][ni][2], c3 = acc[mi][ni][3];
            if (MODE == 1) {
                const float bx = bias[n], by = bias[n + 1];
                *(float2*)(C + (size_t)m0 * Dd + n) = make_float2(c0 + bx, c1 + by);
                *(float2*)(C + (size_t)(m0 + 8) * Dd + n) = make_float2(c2 + bx, c3 + by);
            } else {
                const int h_ = n >> 6, d_ = n & 63;
                uint32_t h01, l01;
                {
                    split2(c0, c1, h01, l01);
                    const int b_ = m0 >> 11, t_ = m0 & (Ts - 1);
                    const size_t idx = (((((size_t)(b_ * Hh + h_) * Ts + t_) << 6) + d_) >> 1);
                    Ch[idx] = h01; Cl[idx] = l01;
                }
                {
                    split2(c2, c3, h01, l01);
                    const int m1 = m0 + 8;
                    const int b_ = m1 >> 11, t_ = m1 & (Ts - 1);
                    const size_t idx = (((((size_t)(b_ * Hh + h_) * Ts + t_) << 6) + d_) >> 1);
                    Ch[idx] = h01; Cl[idx] = l01;
                }
            }
        }
    }
}

__global__ void __launch_bounds__(256) gemm_qkv() {
    const int z = blockIdx.z;
    gemm_core<0>(g_Xh[z], g_Xl[z], g_Wh[z], g_Wl[z],
                 (uint32_t*)g_Ph[z], (uint32_t*)g_Pl[z], nullptr, nullptr);
}
__global__ void __launch_bounds__(256) gemm_out(float* C, const float* bias) {
    gemm_core<1>(g_Ah, g_Al, g_Wh[3], g_Wl[3], nullptr, nullptr, C, bias);
}

// ---------------------------------------------------------------------------
// Flash attention, bf16x3 MMA, cp.async double-buffered K/V.
// CTA: 64 queries x one (b,h); 128 threads (4 warps x 16 q-rows);
// key blocks of 64. SMEM: Q hi/lo + 2 stages of (K,V) hi/lo = 92160 B.
// ---------------------------------------------------------------------------
constexpr int FSTR = 72;                       // bf16 row stride (36 u32)
constexpr int FQ_H = 0;
constexpr int FQ_L = 64 * FSTR;                // 4608 (bf16 elems)
constexpr int FST0 = 2 * 64 * FSTR;            // 9216
constexpr int FSTAGE = 4 * 64 * FSTR;          // 18432 bf16 per stage
constexpr int FKH = 0, FKL = 64 * FSTR, FVH = 2 * 64 * FSTR, FVL = 3 * 64 * FSTR;
constexpr int F_SMEM_BYTES = (FST0 + 2 * FSTAGE) * 2;  // 92160

__global__ void __launch_bounds__(128, 2) flash_mma() {
    extern __shared__ __nv_bfloat16 fsm[];
    const uint32_t smb = smem_u32(fsm);
    const int tid = threadIdx.x;
    const int lane = tid & 31;
    const int w = tid >> 5;
    const int g = lane >> 2;
    const int t = lane & 3;
    const int qb = blockIdx.x;   // 0..31 (64-query blocks)
    const int bh = blockIdx.y;
    const int q0 = qb * 64;

    const int row_off = lane & 7, sel = lane >> 3;
    const uint32_t aoffF = ((uint32_t)(row_off + 8 * (sel & 1)) * 36 + (sel >> 1) * 4) * 4;
    const uint32_t boffF = ((uint32_t)(row_off + 8 * (sel >> 1)) * 36 + (sel & 1) * 4) * 4;

    const __nv_bfloat16* Qh = g_Ph[0] + (size_t)bh * Ts * HD;
    const __nv_bfloat16* Ql = g_Pl[0] + (size_t)bh * Ts * HD;
    const __nv_bfloat16* Kh = g_Ph[1] + (size_t)bh * Ts * HD;
    const __nv_bfloat16* Kl = g_Pl[1] + (size_t)bh * Ts * HD;
    const __nv_bfloat16* Vh = g_Ph[2] + (size_t)bh * Ts * HD;
    const __nv_bfloat16* Vl = g_Pl[2] + (size_t)bh * Ts * HD;

    const int lrow = tid >> 3, lch = tid & 7;  // 16 rows/pass, 8x16B chunks/row

    // ---- issue Q copies (group 0, together with K/V stage 0) ----
#pragma unroll
    for (int i = 0; i < 4; i++) {
        const int row = lrow + i * 16;
        const size_t go = (size_t)(q0 + row) * HD + lch * 8;
        const uint32_t doff = (uint32_t)(row * FSTR) * 2 + lch * 16;
        cpasync16(smb + doff, Qh + go);
        cpasync16(smb + FQ_L * 2 + doff, Ql + go);
    }
    auto issueKV = [&](int kb, int st) {
        const uint32_t base = smb + (uint32_t)(FST0 + st * FSTAGE) * 2;
#pragma unroll
        for (int i = 0; i < 4; i++) {
            const int row = lrow + i * 16;
            const size_t go = (size_t)(kb * 64 + row) * HD + lch * 8;
            const uint32_t doff = (uint32_t)(row * FSTR) * 2 + lch * 16;
            cpasync16(base + FKH * 2 + doff, Kh + go);
            cpasync16(base + FKL * 2 + doff, Kl + go);
            cpasync16(base + FVH * 2 + doff, Vh + go);
            cpasync16(base + FVL * 2 + doff, Vl + go);
        }
    };
    issueKV(0, 0);
    CP_COMMIT();

    uint32_t qh[4][4], ql[4][4];
    const int r0 = q0 + w * 16 + g;
    const int r1 = r0 + 8;

    float o[8][4];
#pragma unroll
    for (int nb = 0; nb < 8; nb++)
#pragma unroll
        for (int r = 0; r < 4; r++) o[nb][r] = 0.f;
    float m0 = -1e30f, m1 = -1e30f, l0 = 0.f, l1 = 0.f;

    const int nkb = qb + 1;
    for (int kb = 0; kb < nkb; kb++) {
        const int st = kb & 1;
        if (kb + 1 < nkb) {
            issueKV(kb + 1, st ^ 1);
            CP_COMMIT();
            CP_WAIT(1);
        } else {
            CP_WAIT(0);
        }
        __syncthreads();

        if (kb == 0) {
            // Q fragments (persist across key blocks)
#pragma unroll
            for (int ks = 0; ks < 4; ks++) {
                const uint32_t qd = (uint32_t)((w * 16) * 36 + ks * 8) * 4;
                ldmx4(qh[ks], smb + qd + aoffF);
                ldmx4(ql[ks], smb + FQ_L * 2 + qd + aoffF);  // Q-lo at byte off FQ_L*2
            }
        }

        const uint32_t bKH = smb + (uint32_t)(FST0 + st * FSTAGE + FKH) * 2;
        const uint32_t bKL = smb + (uint32_t)(FST0 + st * FSTAGE + FKL) * 2;
        const uint32_t bVH = smb + (uint32_t)(FST0 + st * FSTAGE + FVH) * 2;
        const uint32_t bVL = smb + (uint32_t)(FST0 + st * FSTAGE + FVL) * 2;

        // ---- S = Q . K^T ----
        float s[8][4];
#pragma unroll
        for (int nb = 0; nb < 8; nb++)
#pragma unroll
            for (int r = 0; r < 4; r++) s[nb][r] = 0.f;
#pragma unroll
        for (int ks = 0; ks < 4; ks++) {
#pragma unroll
            for (int np = 0; np < 4; np++) {
                const uint32_t kd = (uint32_t)((np * 16) * 36 + ks * 8) * 4;
                uint32_t kh4[4], kl4[4];
                ldmx4(kh4, bKH + kd + boffF);
                ldmx4(kl4, bKL + kd + boffF);
                mma_bf16(s[2 * np], qh[ks], kh4);
                mma_bf16(s[2 * np], qh[ks], kl4);
                mma_bf16(s[2 * np], ql[ks], kh4);
                mma_bf16(s[2 * np + 1], qh[ks], kh4 + 2);
                mma_bf16(s[2 * np + 1], qh[ks], kl4 + 2);
                mma_bf16(s[2 * np + 1], ql[ks], kh4 + 2);
            }
        }

        // ---- causal mask (diagonal block only) ----
        if (kb == qb) {
            const int k0 = kb * 64;
#pragma unroll
            for (int nb = 0; nb < 8; nb++) {
                const int key0 = k0 + 8 * nb + 2 * t;
                if (key0 > r0) s[nb][0] = -1e30f;
                if (key0 + 1 > r0) s[nb][1] = -1e30f;
                if (key0 > r1) s[nb][2] = -1e30f;
                if (key0 + 1 > r1) s[nb][3] = -1e30f;
            }
        }

        // ---- online softmax (quad-local) ----
        float rm0 = -1e30f, rm1 = -1e30f;
#pragma unroll
        for (int nb = 0; nb < 8; nb++) {
            rm0 = fmaxf(rm0, fmaxf(s[nb][0], s[nb][1]));
            rm1 = fmaxf(rm1, fmaxf(s[nb][2], s[nb][3]));
        }
#pragma unroll
        for (int off = 1; off < 4; off <<= 1) {
            rm0 = fmaxf(rm0, __shfl_xor_sync(0xffffffffu, rm0, off));
            rm1 = fmaxf(rm1, __shfl_xor_sync(0xffffffffu, rm1, off));
        }
        const float nm0 = fmaxf(m0, rm0), nm1 = fmaxf(m1, rm1);
        const float corr0 = __expf(m0 - nm0), corr1 = __expf(m1 - nm1);
        m0 = nm0; m1 = nm1;
        float sum0 = 0.f, sum1 = 0.f;
#pragma unroll
        for (int nb = 0; nb < 8; nb++) {
            s[nb][0] = __expf(s[nb][0] - m0);
            s[nb][1] = __expf(s[nb][1] - m0);
            s[nb][2] = __expf(s[nb][2] - m1);
            s[nb][3] = __expf(s[nb][3] - m1);
            sum0 += s[nb][0] + s[nb][1];
            sum1 += s[nb][2] + s[nb][3];
        }
#pragma unroll
        for (int off = 1; off < 4; off <<= 1) {
            sum0 += __shfl_xor_sync(0xffffffffu, sum0, off);
            sum1 += __shfl_xor_sync(0xffffffffu, sum1, off);
        }
        l0 = l0 * corr0 + sum0;
        l1 = l1 * corr1 + sum1;
#pragma unroll
        for (int nb = 0; nb < 8; nb++) {
            o[nb][0] *= corr0;
            o[nb][1] *= corr0;
            o[nb][2] *= corr1;
            o[nb][3] *= corr1;
        }

        // ---- O += P . V ----
#pragma unroll
        for (int stp = 0; stp < 4; stp++) {
            uint32_t ph[4], pl[4];
            split2(s[2 * stp][0], s[2 * stp][1], ph[0], pl[0]);
            split2(s[2 * stp][2], s[2 * stp][3], ph[1], pl[1]);
            split2(s[2 * stp + 1][0], s[2 * stp + 1][1], ph[2], pl[2]);
            split2(s[2 * stp + 1][2], s[2 * stp + 1][3], ph[3], pl[3]);
#pragma unroll
            for (int p = 0; p < 4; p++) {
                const uint32_t vd = (uint32_t)((16 * stp) * 36 + p * 8) * 4;
                uint32_t vh4[4], vl4[4];
                ldmx4t(vh4, bVH + vd + aoffF);
                ldmx4t(vl4, bVL + vd + aoffF);
                mma_bf16(o[2 * p], ph, vh4);
                mma_bf16(o[2 * p], ph, vl4);
                mma_bf16(o[2 * p], pl, vh4);
                mma_bf16(o[2 * p + 1], ph, vh4 + 2);
                mma_bf16(o[2 * p + 1], ph, vl4 + 2);
                mma_bf16(o[2 * p + 1], pl, vh4 + 2);
            }
        }
        __syncthreads();
    }

    // ---- epilogue ----
    const int b_ = bh >> 4;
    const int h_ = bh & 15;
    const float inv0 = 1.f / l0, inv1 = 1.f / l1;
    uint32_t* gAh = (uint32_t*)g_Ah;
    uint32_t* gAl = (uint32_t*)g_Al;
#pragma unroll
    for (int nb = 0; nb < 8; nb++) {
        const int col = h_ * 64 + 8 * nb + 2 * t;
        uint32_t h01, l01;
        split2(o[nb][0] * inv0, o[nb][1] * inv0, h01, l01);
        size_t idx = (((size_t)(b_ * Ts + r0)) * Dd + col) >> 1;
        gAh[idx] = h01; gAl[idx] = l01;
        split2(o[nb][2] * inv1, o[nb][3] * inv1, h01, l01);
        idx = (((size_t)(b_ * Ts + r1)) * Dd + col) >> 1;
        gAh[idx] = h01; gAl[idx] = l01;
    }
}

// ---------------------------------------------------------------------------
extern "C" void kernel_launch(void* const* d_in, const int* in_sizes, int n_in,
                              void* d_out, int out_size) {
    const float* xin[3] = {(const float*)d_in[0], (const float*)d_in[1],
                           (const float*)d_in[2]};
    const float* win[4] = {(const float*)d_in[3], (const float*)d_in[4],
                           (const float*)d_in[5], (const float*)d_in[6]};
    const float* bo = (const float*)d_in[7];
    float* out = (float*)d_out;

    __nv_bfloat16 *pXh, *pXl, *pWh, *pWl;
    cudaGetSymbolAddress((void**)&pXh, g_Xh);
    cudaGetSymbolAddress((void**)&pXl, g_Xl);
    cudaGetSymbolAddress((void**)&pWh, g_Wh);
    cudaGetSymbolAddress((void**)&pWl, g_Wl);

    cudaFuncSetAttribute(gemm_qkv, cudaFuncAttributeMaxDynamicSharedMemorySize, GEMM_SMEM);
    cudaFuncSetAttribute(gemm_out, cudaFuncAttributeMaxDynamicSharedMemorySize, GEMM_SMEM);
    cudaFuncSetAttribute(flash_mma, cudaFuncAttributeMaxDynamicSharedMemorySize, F_SMEM_BYTES);

    for (int z = 0; z < 3; z++)
        cvt_split<<<(int)(XSZ / 4 / 256), 256>>>(
            (const float4*)xin[z], (uint2*)(pXh + z * XSZ), (uint2*)(pXl + z * XSZ),
            (int)(XSZ / 4), 1.f);
    for (int z = 0; z < 4; z++)
        cvt_split<<<(int)(WSZ / 4 / 256), 256>>>(
            (const float4*)win[z], (uint2*)(pWh + z * WSZ), (uint2*)(pWl + z * WSZ),
            (int)(WSZ / 4), z == 0 ? 0.125f : 1.f);

    gemm_qkv<<<dim3(Dd / 128, Mrows / 128, 3), 256, GEMM_SMEM>>>();
    flash_mma<<<dim3(Ts / 64, Bb * Hh), 128, F_SMEM_BYTES>>>();
    gemm_out<<<dim3(Dd / 128, Mrows / 128), 256, GEMM_SMEM>>>(out, bo);
}

// round 8
// speedup vs baseline: 3.2354x; 1.0357x over previous
#include <cuda_runtime.h>
#include <cuda_bf16.h>
#include <cstdint>

// Fixed problem shape
constexpr int Bb = 4;
constexpr int Ts = 2048;
constexpr int Dd = 1024;
constexpr int Hh = 16;
constexpr int HD = 64;
constexpr int Mrows = Bb * Ts;               // 8192
constexpr size_t XSZ = (size_t)Mrows * Dd;   // 8388608
constexpr size_t WSZ = (size_t)Dd * Dd;      // 1048576

// Device scratch: everything bf16 hi/lo after the prep pass.
__device__ __nv_bfloat16 g_Xh[3][XSZ], g_Xl[3][XSZ];
__device__ __nv_bfloat16 g_Wh[4][WSZ], g_Wl[4][WSZ];
__device__ __nv_bfloat16 g_Ph[3][XSZ], g_Pl[3][XSZ];
__device__ __nv_bfloat16 g_Ah[XSZ], g_Al[XSZ];

// ---------------------------------------------------------------------------
// Helpers
// ---------------------------------------------------------------------------
__device__ __forceinline__ void mma_bf16(float* d, const uint32_t* a, const uint32_t* b) {
    asm volatile(
        "mma.sync.aligned.m16n8k16.row.col.f32.bf16.bf16.f32 "
        "{%0,%1,%2,%3}, {%4,%5,%6,%7}, {%8,%9}, {%0,%1,%2,%3};"
        : "+f"(d[0]), "+f"(d[1]), "+f"(d[2]), "+f"(d[3])
        : "r"(a[0]), "r"(a[1]), "r"(a[2]), "r"(a[3]), "r"(b[0]), "r"(b[1]));
}
__device__ __forceinline__ void split2(float a, float b, uint32_t& h, uint32_t& l) {
    __nv_bfloat162 hb = __floats2bfloat162_rn(a, b);
    float2 hf = __bfloat1622float2(hb);
    __nv_bfloat162 lb = __floats2bfloat162_rn(a - hf.x, b - hf.y);
    h = *(uint32_t*)&hb;
    l = *(uint32_t*)&lb;
}
__device__ __forceinline__ uint32_t smem_u32(const void* p) {
    uint32_t a;
    asm("{ .reg .u64 t; cvta.to.shared.u64 t, %1; cvt.u32.u64 %0, t; }" : "=r"(a) : "l"(p));
    return a;
}
__device__ __forceinline__ void ldmx4(uint32_t* r, uint32_t addr) {
    asm volatile("ldmatrix.sync.aligned.m8n8.x4.shared.b16 {%0,%1,%2,%3}, [%4];"
                 : "=r"(r[0]), "=r"(r[1]), "=r"(r[2]), "=r"(r[3]) : "r"(addr));
}
__device__ __forceinline__ void ldmx4t(uint32_t* r, uint32_t addr) {
    asm volatile("ldmatrix.sync.aligned.m8n8.x4.trans.shared.b16 {%0,%1,%2,%3}, [%4];"
                 : "=r"(r[0]), "=r"(r[1]), "=r"(r[2]), "=r"(r[3]) : "r"(addr));
}
__device__ __forceinline__ void cpasync16(uint32_t dst, const void* src) {
    asm volatile("cp.async.cg.shared.global [%0], [%1], 16;" ::"r"(dst), "l"(src));
}
#define CP_COMMIT() asm volatile("cp.async.commit_group;" ::: "memory")
#define CP_WAIT(n) asm volatile("cp.async.wait_group %0;" ::"n"(n) : "memory")

// ---------------------------------------------------------------------------
// Prep: fp32 -> (hi, lo) bf16 split. Batched: one launch for X (3 tensors),
// one for W (4 tensors; Wq gets the 0.125 softmax scale folded in).
// ---------------------------------------------------------------------------
__global__ void cvt_split_x(const float4* __restrict__ x0, const float4* __restrict__ x1,
                            const float4* __restrict__ x2) {
    const int z = blockIdx.y;
    const size_t i = (size_t)blockIdx.x * blockDim.x + threadIdx.x;
    const float4* in = z == 0 ? x0 : (z == 1 ? x1 : x2);
    float4 v = in[i];
    uint32_t h01, l01, h23, l23;
    split2(v.x, v.y, h01, l01);
    split2(v.z, v.w, h23, l23);
    ((uint2*)g_Xh[z])[i] = make_uint2(h01, h23);
    ((uint2*)g_Xl[z])[i] = make_uint2(l01, l23);
}
__global__ void cvt_split_w(const float4* __restrict__ w0, const float4* __restrict__ w1,
                            const float4* __restrict__ w2, const float4* __restrict__ w3) {
    const int z = blockIdx.y;
    const size_t i = (size_t)blockIdx.x * blockDim.x + threadIdx.x;
    const float4* in = z == 0 ? w0 : (z == 1 ? w1 : (z == 2 ? w2 : w3));
    const float scale = z == 0 ? 0.125f : 1.f;
    float4 v = in[i];
    v.x *= scale; v.y *= scale; v.z *= scale; v.w *= scale;
    uint32_t h01, l01, h23, l23;
    split2(v.x, v.y, h01, l01);
    split2(v.z, v.w, h23, l23);
    ((uint2*)g_Wh[z])[i] = make_uint2(h01, h23);
    ((uint2*)g_Wl[z])[i] = make_uint2(l01, l23);
}

// ---------------------------------------------------------------------------
// bf16x3 GEMM, cp.async double-buffered, ONE barrier per k-chunk.
// C = A @ B^T, M=8192, N=K=1024. 128x128 tile, BK=32, 256 threads.
// ---------------------------------------------------------------------------
constexpr int RS = 20;                 // padded row stride (u32)
constexpr int TILE_U32 = 128 * RS;
constexpr int GEMM_SMEM = 8 * TILE_U32 * 4;  // 81920 B

template <int MODE>
__device__ __forceinline__ void gemm_core(
    const __nv_bfloat16* __restrict__ Ah, const __nv_bfloat16* __restrict__ Al,
    const __nv_bfloat16* __restrict__ Bh, const __nv_bfloat16* __restrict__ Bl,
    uint32_t* __restrict__ Ch, uint32_t* __restrict__ Cl,
    float* __restrict__ C, const float* __restrict__ bias) {
    extern __shared__ uint32_t sm[];
    const uint32_t smb = smem_u32(sm);
    const int tid = threadIdx.x, lane = tid & 31, warp = tid >> 5;
    const int bm = blockIdx.y * 128, bn = blockIdx.x * 128;
    const int wm = (warp >> 2) * 64, wn = (warp & 3) * 32;
    const int row_off = lane & 7, sel = lane >> 3;
    const uint32_t aoff = ((uint32_t)(row_off + 8 * (sel & 1)) * RS + (sel >> 1) * 4) * 4;
    const uint32_t boff = ((uint32_t)(row_off + 8 * (sel >> 1)) * RS + (sel & 1) * 4) * 4;
    const int lrow = tid >> 2, lch = tid & 3;

    float acc[4][4][4];
#pragma unroll
    for (int mi = 0; mi < 4; mi++)
#pragma unroll
        for (int ni = 0; ni < 4; ni++)
#pragma unroll
            for (int r = 0; r < 4; r++) acc[mi][ni][r] = 0.f;

    auto issue = [&](int kc, int st) {
        const uint32_t base = smb + (uint32_t)st * 4 * TILE_U32 * 4;
#pragma unroll
        for (int i = 0; i < 2; i++) {
            const int row = lrow + i * 64;
            const uint32_t doff = (uint32_t)(row * RS + lch * 4) * 4;
            const size_t asrc = (size_t)(bm + row) * Dd + kc * 32 + lch * 8;
            const size_t bsrc = (size_t)(bn + row) * Dd + kc * 32 + lch * 8;
            cpasync16(base + 0 * TILE_U32 * 4 + doff, Ah + asrc);
            cpasync16(base + 1 * TILE_U32 * 4 + doff, Al + asrc);
            cpasync16(base + 2 * TILE_U32 * 4 + doff, Bh + bsrc);
            cpasync16(base + 3 * TILE_U32 * 4 + doff, Bl + bsrc);
        }
    };

    issue(0, 0);
    CP_COMMIT();

    for (int kc = 0; kc < Dd / 32; kc++) {
        const int st = kc & 1;
        CP_WAIT(0);
        __syncthreads();   // all warps done reading stage st^1 (prev iter)
        if (kc + 1 < Dd / 32) {
            issue(kc + 1, st ^ 1);   // overlaps the whole compute below
            CP_COMMIT();
        }

        const uint32_t bAh = smb + (st * 4 + 0) * TILE_U32 * 4;
        const uint32_t bAl = smb + (st * 4 + 1) * TILE_U32 * 4;
        const uint32_t bBh = smb + (st * 4 + 2) * TILE_U32 * 4;
        const uint32_t bBl = smb + (st * 4 + 3) * TILE_U32 * 4;
#pragma unroll
        for (int ks = 0; ks < 2; ks++) {
            uint32_t ah[4][4], al[4][4], bh[4][2], bl[4][2];
#pragma unroll
            for (int mi = 0; mi < 4; mi++) {
                const uint32_t ad = (uint32_t)((wm + mi * 16) * RS + ks * 8) * 4;
                ldmx4(ah[mi], bAh + ad + aoff);
                ldmx4(al[mi], bAl + ad + aoff);
            }
#pragma unroll
            for (int np = 0; np < 2; np++) {
                const uint32_t bd = (uint32_t)((wn + np * 16) * RS + ks * 8) * 4;
                uint32_t t4[4];
                ldmx4(t4, bBh + bd + boff);
                bh[2 * np][0] = t4[0]; bh[2 * np][1] = t4[1];
                bh[2 * np + 1][0] = t4[2]; bh[2 * np + 1][1] = t4[3];
                ldmx4(t4, bBl + bd + boff);
                bl[2 * np][0] = t4[0]; bl[2 * np][1] = t4[1];
                bl[2 * np + 1][0] = t4[2]; bl[2 * np + 1][1] = t4[3];
            }
#pragma unroll
            for (int mi = 0; mi < 4; mi++)
#pragma unroll
                for (int ni = 0; ni < 4; ni++) {
                    mma_bf16(acc[mi][ni], ah[mi], bh[ni]);
                    mma_bf16(acc[mi][ni], ah[mi], bl[ni]);
                    mma_bf16(acc[mi][ni], al[mi], bh[ni]);
                }
        }
    }

    const int g = lane >> 2, t = lane & 3;
#pragma unroll
    for (int mi = 0; mi < 4; mi++) {
        const int m0 = bm + wm + mi * 16 + g;
#pragma unroll
        for (int ni = 0; ni < 4; ni++) {
            const int n = bn + wn + ni * 8 + 2 * t;
            const float c0 = acc[mi][ni][0], c1 = acc[mi][ni][1];
            const float c2 = acc[mi][ni][2], c3 = acc[mi][ni][3];
            if (MODE == 1) {
                const float bx = bias[n], by = bias[n + 1];
                *(float2*)(C + (size_t)m0 * Dd + n) = make_float2(c0 + bx, c1 + by);
                *(float2*)(C + (size_t)(m0 + 8) * Dd + n) = make_float2(c2 + bx, c3 + by);
            } else {
                const int h_ = n >> 6, d_ = n & 63;
                uint32_t h01, l01;
                {
                    split2(c0, c1, h01, l01);
                    const int b_ = m0 >> 11, t_ = m0 & (Ts - 1);
                    const size_t idx = (((((size_t)(b_ * Hh + h_) * Ts + t_) << 6) + d_) >> 1);
                    Ch[idx] = h01; Cl[idx] = l01;
                }
                {
                    split2(c2, c3, h01, l01);
                    const int m1 = m0 + 8;
                    const int b_ = m1 >> 11, t_ = m1 & (Ts - 1);
                    const size_t idx = (((((size_t)(b_ * Hh + h_) * Ts + t_) << 6) + d_) >> 1);
                    Ch[idx] = h01; Cl[idx] = l01;
                }
            }
        }
    }
}

__global__ void __launch_bounds__(256) gemm_qkv() {
    const int z = blockIdx.z;
    gemm_core<0>(g_Xh[z], g_Xl[z], g_Wh[z], g_Wl[z],
                 (uint32_t*)g_Ph[z], (uint32_t*)g_Pl[z], nullptr, nullptr);
}
__global__ void __launch_bounds__(256) gemm_out(float* C, const float* bias) {
    gemm_core<1>(g_Ah, g_Al, g_Wh[3], g_Wl[3], nullptr, nullptr, C, bias);
}

// ---------------------------------------------------------------------------
// Flash attention, bf16x3 MMA, cp.async double-buffered K/V, ONE barrier
// per key block. CTA: 64 queries x one (b,h); 128 threads; SMEM 92160 B.
// ---------------------------------------------------------------------------
constexpr int FSTR = 72;                       // bf16 row stride (36 u32)
constexpr int FQ_L = 64 * FSTR;                // 4608 (bf16 elems)
constexpr int FST0 = 2 * 64 * FSTR;            // 9216
constexpr int FSTAGE = 4 * 64 * FSTR;          // 18432 bf16 per stage
constexpr int FKH = 0, FKL = 64 * FSTR, FVH = 2 * 64 * FSTR, FVL = 3 * 64 * FSTR;
constexpr int F_SMEM_BYTES = (FST0 + 2 * FSTAGE) * 2;  // 92160

__global__ void __launch_bounds__(128, 2) flash_mma() {
    extern __shared__ __nv_bfloat16 fsm[];
    const uint32_t smb = smem_u32(fsm);
    const int tid = threadIdx.x;
    const int lane = tid & 31;
    const int w = tid >> 5;
    const int g = lane >> 2;
    const int t = lane & 3;
    const int qb = blockIdx.x;
    const int bh = blockIdx.y;
    const int q0 = qb * 64;

    const int row_off = lane & 7, sel = lane >> 3;
    const uint32_t aoffF = ((uint32_t)(row_off + 8 * (sel & 1)) * 36 + (sel >> 1) * 4) * 4;
    const uint32_t boffF = ((uint32_t)(row_off + 8 * (sel >> 1)) * 36 + (sel & 1) * 4) * 4;

    const __nv_bfloat16* Qh = g_Ph[0] + (size_t)bh * Ts * HD;
    const __nv_bfloat16* Ql = g_Pl[0] + (size_t)bh * Ts * HD;
    const __nv_bfloat16* Kh = g_Ph[1] + (size_t)bh * Ts * HD;
    const __nv_bfloat16* Kl = g_Pl[1] + (size_t)bh * Ts * HD;
    const __nv_bfloat16* Vh = g_Ph[2] + (size_t)bh * Ts * HD;
    const __nv_bfloat16* Vl = g_Pl[2] + (size_t)bh * Ts * HD;

    const int lrow = tid >> 3, lch = tid & 7;

    // Q copies go in the same group as K/V stage 0
#pragma unroll
    for (int i = 0; i < 4; i++) {
        const int row = lrow + i * 16;
        const size_t go = (size_t)(q0 + row) * HD + lch * 8;
        const uint32_t doff = (uint32_t)(row * FSTR) * 2 + lch * 16;
        cpasync16(smb + doff, Qh + go);
        cpasync16(smb + FQ_L * 2 + doff, Ql + go);
    }
    auto issueKV = [&](int kb, int st) {
        const uint32_t base = smb + (uint32_t)(FST0 + st * FSTAGE) * 2;
#pragma unroll
        for (int i = 0; i < 4; i++) {
            const int row = lrow + i * 16;
            const size_t go = (size_t)(kb * 64 + row) * HD + lch * 8;
            const uint32_t doff = (uint32_t)(row * FSTR) * 2 + lch * 16;
            cpasync16(base + FKH * 2 + doff, Kh + go);
            cpasync16(base + FKL * 2 + doff, Kl + go);
            cpasync16(base + FVH * 2 + doff, Vh + go);
            cpasync16(base + FVL * 2 + doff, Vl + go);
        }
    };
    issueKV(0, 0);
    CP_COMMIT();

    uint32_t qh[4][4], ql[4][4];
    const int r0 = q0 + w * 16 + g;
    const int r1 = r0 + 8;

    float o[8][4];
#pragma unroll
    for (int nb = 0; nb < 8; nb++)
#pragma unroll
        for (int r = 0; r < 4; r++) o[nb][r] = 0.f;
    float m0 = -1e30f, m1 = -1e30f, l0 = 0.f, l1 = 0.f;

    const int nkb = qb + 1;
    for (int kb = 0; kb < nkb; kb++) {
        const int st = kb & 1;
        CP_WAIT(0);
        __syncthreads();   // all warps done reading stage st^1 (prev iter)
        if (kb + 1 < nkb) {
            issueKV(kb + 1, st ^ 1);   // overlaps compute below
            CP_COMMIT();
        }

        if (kb == 0) {
#pragma unroll
            for (int ks = 0; ks < 4; ks++) {
                const uint32_t qd = (uint32_t)((w * 16) * 36 + ks * 8) * 4;
                ldmx4(qh[ks], smb + qd + aoffF);
                ldmx4(ql[ks], smb + FQ_L * 2 + qd + aoffF);
            }
        }

        const uint32_t bKH = smb + (uint32_t)(FST0 + st * FSTAGE + FKH) * 2;
        const uint32_t bKL = smb + (uint32_t)(FST0 + st * FSTAGE + FKL) * 2;
        const uint32_t bVH = smb + (uint32_t)(FST0 + st * FSTAGE + FVH) * 2;
        const uint32_t bVL = smb + (uint32_t)(FST0 + st * FSTAGE + FVL) * 2;

        // ---- S = Q . K^T ----
        float s[8][4];
#pragma unroll
        for (int nb = 0; nb < 8; nb++)
#pragma unroll
            for (int r = 0; r < 4; r++) s[nb][r] = 0.f;
#pragma unroll
        for (int ks = 0; ks < 4; ks++) {
#pragma unroll
            for (int np = 0; np < 4; np++) {
                const uint32_t kd = (uint32_t)((np * 16) * 36 + ks * 8) * 4;
                uint32_t kh4[4], kl4[4];
                ldmx4(kh4, bKH + kd + boffF);
                ldmx4(kl4, bKL + kd + boffF);
                mma_bf16(s[2 * np], qh[ks], kh4);
                mma_bf16(s[2 * np], qh[ks], kl4);
                mma_bf16(s[2 * np], ql[ks], kh4);
                mma_bf16(s[2 * np + 1], qh[ks], kh4 + 2);
                mma_bf16(s[2 * np + 1], qh[ks], kl4 + 2);
                mma_bf16(s[2 * np + 1], ql[ks], kh4 + 2);
            }
        }

        // ---- causal mask (diagonal block only) ----
        if (kb == qb) {
            const int k0 = kb * 64;
#pragma unroll
            for (int nb = 0; nb < 8; nb++) {
                const int key0 = k0 + 8 * nb + 2 * t;
                if (key0 > r0) s[nb][0] = -1e30f;
                if (key0 + 1 > r0) s[nb][1] = -1e30f;
                if (key0 > r1) s[nb][2] = -1e30f;
                if (key0 + 1 > r1) s[nb][3] = -1e30f;
            }
        }

        // ---- online softmax (quad-local) ----
        float rm0 = -1e30f, rm1 = -1e30f;
#pragma unroll
        for (int nb = 0; nb < 8; nb++) {
            rm0 = fmaxf(rm0, fmaxf(s[nb][0], s[nb][1]));
            rm1 = fmaxf(rm1, fmaxf(s[nb][2], s[nb][3]));
        }
#pragma unroll
        for (int off = 1; off < 4; off <<= 1) {
            rm0 = fmaxf(rm0, __shfl_xor_sync(0xffffffffu, rm0, off));
            rm1 = fmaxf(rm1, __shfl_xor_sync(0xffffffffu, rm1, off));
        }
        const float nm0 = fmaxf(m0, rm0), nm1 = fmaxf(m1, rm1);
        const float corr0 = __expf(m0 - nm0), corr1 = __expf(m1 - nm1);
        m0 = nm0; m1 = nm1;
        float sum0 = 0.f, sum1 = 0.f;
#pragma unroll
        for (int nb = 0; nb < 8; nb++) {
            s[nb][0] = __expf(s[nb][0] - m0);
            s[nb][1] = __expf(s[nb][1] - m0);
            s[nb][2] = __expf(s[nb][2] - m1);
            s[nb][3] = __expf(s[nb][3] - m1);
            sum0 += s[nb][0] + s[nb][1];
            sum1 += s[nb][2] + s[nb][3];
        }
#pragma unroll
        for (int off = 1; off < 4; off <<= 1) {
            sum0 += __shfl_xor_sync(0xffffffffu, sum0, off);
            sum1 += __shfl_xor_sync(0xffffffffu, sum1, off);
        }
        l0 = l0 * corr0 + sum0;
        l1 = l1 * corr1 + sum1;
#pragma unroll
        for (int nb = 0; nb < 8; nb++) {
            o[nb][0] *= corr0;
            o[nb][1] *= corr0;
            o[nb][2] *= corr1;
            o[nb][3] *= corr1;
        }

        // ---- O += P . V ----
#pragma unroll
        for (int stp = 0; stp < 4; stp++) {
            uint32_t ph[4], pl[4];
            split2(s[2 * stp][0], s[2 * stp][1], ph[0], pl[0]);
            split2(s[2 * stp][2], s[2 * stp][3], ph[1], pl[1]);
            split2(s[2 * stp + 1][0], s[2 * stp + 1][1], ph[2], pl[2]);
            split2(s[2 * stp + 1][2], s[2 * stp + 1][3], ph[3], pl[3]);
#pragma unroll
            for (int p = 0; p < 4; p++) {
                const uint32_t vd = (uint32_t)((16 * stp) * 36 + p * 8) * 4;
                uint32_t vh4[4], vl4[4];
                ldmx4t(vh4, bVH + vd + aoffF);
                ldmx4t(vl4, bVL + vd + aoffF);
                mma_bf16(o[2 * p], ph, vh4);
                mma_bf16(o[2 * p], ph, vl4);
                mma_bf16(o[2 * p], pl, vh4);
                mma_bf16(o[2 * p + 1], ph, vh4 + 2);
                mma_bf16(o[2 * p + 1], ph, vl4 + 2);
                mma_bf16(o[2 * p + 1], pl, vh4 + 2);
            }
        }
    }

    // ---- epilogue ----
    const int b_ = bh >> 4;
    const int h_ = bh & 15;
    const float inv0 = 1.f / l0, inv1 = 1.f / l1;
    uint32_t* gAh = (uint32_t*)g_Ah;
    uint32_t* gAl = (uint32_t*)g_Al;
#pragma unroll
    for (int nb = 0; nb < 8; nb++) {
        const int col = h_ * 64 + 8 * nb + 2 * t;
        uint32_t h01, l01;
        split2(o[nb][0] * inv0, o[nb][1] * inv0, h01, l01);
        size_t idx = (((size_t)(b_ * Ts + r0)) * Dd + col) >> 1;
        gAh[idx] = h01; gAl[idx] = l01;
        split2(o[nb][2] * inv1, o[nb][3] * inv1, h01, l01);
        idx = (((size_t)(b_ * Ts + r1)) * Dd + col) >> 1;
        gAh[idx] = h01; gAl[idx] = l01;
    }
}

// ---------------------------------------------------------------------------
extern "C" void kernel_launch(void* const* d_in, const int* in_sizes, int n_in,
                              void* d_out, int out_size) {
    const float* bo = (const float*)d_in[7];
    float* out = (float*)d_out;

    cudaFuncSetAttribute(gemm_qkv, cudaFuncAttributeMaxDynamicSharedMemorySize, GEMM_SMEM);
    cudaFuncSetAttribute(gemm_out, cudaFuncAttributeMaxDynamicSharedMemorySize, GEMM_SMEM);
    cudaFuncSetAttribute(flash_mma, cudaFuncAttributeMaxDynamicSharedMemorySize, F_SMEM_BYTES);

    cvt_split_x<<<dim3((unsigned)(XSZ / 4 / 256), 3), 256>>>(
        (const float4*)d_in[0], (const float4*)d_in[1], (const float4*)d_in[2]);
    cvt_split_w<<<dim3((unsigned)(WSZ / 4 / 256), 4), 256>>>(
        (const float4*)d_in[3], (const float4*)d_in[4],
        (const float4*)d_in[5], (const float4*)d_in[6]);

    gemm_qkv<<<dim3(Dd / 128, Mrows / 128, 3), 256, GEMM_SMEM>>>();
    flash_mma<<<dim3(Ts / 64, Bb * Hh), 128, F_SMEM_BYTES>>>();
    gemm_out<<<dim3(Dd / 128, Mrows / 128), 256, GEMM_SMEM>>>(out, bo);
}